// round 12
// baseline (speedup 1.0000x reference)
#include <cuda_runtime.h>
#include <cuda_bf16.h>
#include <cstdint>
#include <math.h>

#define NN 50000
#define NE 800000
#define NG 1024

typedef __nv_bfloat16 bf16;
typedef __nv_bfloat162 bf162;

// ---------------- scratch (device globals; no allocation allowed) ----------------
__device__ float g_x [NN*128];
__device__ float g_y [NN*128];
__device__ float g_z [NN*128];
__device__ float g_t1[NN*384];
__device__ float g_t2[NN*384];
__device__ float g_ts[NN];
__device__ float g_rs[NN];
__device__ float g_e [NE];
__device__ int   g_deg[NN];
__device__ int   g_cur[NN];
__device__ int   g_rowptr[NN+1];
__device__ int   g_csr[NE];
__device__ int   g_off[NG+1];
__device__ float g_cb[128];
__device__ float g_gout[NG*128];
__device__ float g_ggh [NG*128];
__device__ float g_goy [NG*128];
__device__ float g_gog1[NG*384];
__device__ float g_gog2[NG*384];
__device__ float g_gad [NG];

// bf16 hi/lo activation buffers
__device__ __align__(16) bf16 g_0hi[NN*64];
__device__ __align__(16) bf16 g_0lo[NN*64];
__device__ __align__(16) bf16 g_xhi[NN*128];
__device__ __align__(16) bf16 g_xlo[NN*128];
__device__ __align__(16) bf16 g_hhi[NN*128];
__device__ __align__(16) bf16 g_hlo[NN*128];

// bf16 hi/lo weight scratch (packed, ld = K)
#define OFF_W1    0
#define OFF_WG1   8192
#define OFF_WG2   24576
#define OFF_WIH0  40960
#define OFF_WHH0  90112
#define OFF_WA    139264
#define OFF_WIHA  172032
#define OFF_WHHA  270336
#define OFF_WM    368640
#define W_TOTAL   385024
__device__ __align__(16) bf16 g_whi[W_TOTAL];
__device__ __align__(16) bf16 g_wlo[W_TOTAL];

// ---------------- helpers ----------------
__device__ __forceinline__ float leakyf(float v){ return v >= 0.f ? v : 0.01f*v; }
__device__ __forceinline__ float sigmf (float v){ return 1.f/(1.f+expf(-v)); }
__device__ __forceinline__ float eluf  (float v){ return v > 0.f ? v : (expf(v)-1.f); }

// =======================================================================
// weight conversion: all 12 node-GEMM weights -> packed bf16 hi/lo
// =======================================================================
struct WPtrs { const float* p[12]; };

__global__ void conv_weights(WPtrs wp)
{
    const int rows[12] = {128,128,128,384,384,128,128,384,384,384,384,128};
    const int cols[12] = { 64,128,128,128,128,128,128,128,128,128,128,128};
    const int ldws[12] = { 64,153,128,128,128,128,128,128,128,128,128,128};
    const int offs[12] = {OFF_W1,OFF_WG1,OFF_WG2,OFF_WIH0,OFF_WHH0,
                          OFF_WA,OFF_WA+16384,OFF_WIHA,OFF_WIHA+49152,
                          OFF_WHHA,OFF_WHHA+49152,OFF_WM};
    int s = blockIdx.y;
    const float* src = wp.p[s];
    int n = rows[s]*cols[s];
    for (int i = blockIdx.x*blockDim.x + threadIdx.x; i < n; i += gridDim.x*blockDim.x) {
        int r = i / cols[s], c = i - r*cols[s];
        float v = src[(size_t)r*ldws[s] + c];
        bf16 h = __float2bfloat16(v);
        g_whi[offs[s] + i] = h;
        g_wlo[offs[s] + i] = __float2bfloat16(v - __bfloat162float(h));
    }
}

__global__ void conv_act(const float* __restrict__ src, bf16* __restrict__ hi,
                         bf16* __restrict__ lo, int n2)
{
    int i = blockIdx.x*blockDim.x + threadIdx.x;
    if (i >= n2) return;
    float2 v = *(const float2*)(src + i*2);
    bf16 hx = __float2bfloat16(v.x), hy = __float2bfloat16(v.y);
    *(bf162*)(hi + i*2) = __halves2bfloat162(hx, hy);
    *(bf162*)(lo + i*2) = __halves2bfloat162(__float2bfloat16(v.x - __bfloat162float(hx)),
                                             __float2bfloat16(v.y - __bfloat162float(hy)));
}

// =======================================================================
// bf16 split-precision tensor-core GEMM, double-buffered cp.async pipeline:
//   C = act(A @ W^T + bias);  D = Ahi*Whi + Ahi*Wlo + Alo*Whi
// BM=128, BN=64, BK=32, 2 stages. Rows interleave hi|lo (32|32, LDA=72).
// 256 thr = 8 warps (4m x 2n), warp tile 32x32. 55296B smem -> 4 CTAs/SM.
// =======================================================================
#define LDA 72                            // 32 hi + 32 lo + 8 pad (bf16 elems)
#define AROWS 128
#define WROWS 64
#define AOFFB (AROWS*LDA*2)               // W section byte offset within stage
#define STAGEB ((AROWS+WROWS)*LDA*2)      // 27648 bytes per stage
#define MM_SMEM (2*STAGEB)                // 55296 bytes

__device__ __forceinline__ void mma16816(float* c, const uint32_t* a, const uint32_t* b){
    asm volatile(
        "mma.sync.aligned.m16n8k16.row.col.f32.bf16.bf16.f32 "
        "{%0,%1,%2,%3}, {%4,%5,%6,%7}, {%8,%9}, {%0,%1,%2,%3};\n"
        : "+f"(c[0]), "+f"(c[1]), "+f"(c[2]), "+f"(c[3])
        : "r"(a[0]), "r"(a[1]), "r"(a[2]), "r"(a[3]), "r"(b[0]), "r"(b[1]));
}
__device__ __forceinline__ void ldsm4(uint32_t* r, uint32_t addr){
    asm volatile("ldmatrix.sync.aligned.m8n8.x4.shared.b16 {%0,%1,%2,%3}, [%4];"
        : "=r"(r[0]), "=r"(r[1]), "=r"(r[2]), "=r"(r[3]) : "r"(addr));
}
__device__ __forceinline__ void cpa16(uint32_t dst, const void* src, int sz){
    asm volatile("cp.async.cg.shared.global [%0], [%1], 16, %2;"
        :: "r"(dst), "l"(src), "r"(sz));
}

__global__ void __launch_bounds__(256, 4)
hgemm_mma(const bf16* __restrict__ Ahi, const bf16* __restrict__ Alo,
          const bf16* __restrict__ Whi, const bf16* __restrict__ Wlo,
          const float* __restrict__ bias, float* __restrict__ C,
          bf16* __restrict__ Chi, bf16* __restrict__ Clo,
          int N, int K, int Ko, int act)
{
    extern __shared__ bf16 sm[];
    const uint32_t usm = (uint32_t)__cvta_generic_to_shared(sm);

    const int tid  = threadIdx.x;
    const int row0 = blockIdx.y * 128;
    const int col0 = blockIdx.x * 64;

    const int wid  = tid >> 5, lane = tid & 31;
    const int wm   = wid & 3,  wn   = wid >> 2;
    const int gid  = lane >> 2, tig = lane & 3;

    const int arow = wm*32 + (lane & 15);
    const int acol = (lane >> 4) << 3;            // 0/8 within 32-col section
    const int brow = wn*32 + ((lane >> 4) << 3) + (lane & 7);
    const int bcol = ((lane >> 3) & 1) << 3;

    float acc[2][4][4];
    #pragma unroll
    for (int mt = 0; mt < 2; mt++)
        #pragma unroll
        for (int nt = 0; nt < 4; nt++)
            #pragma unroll
            for (int q = 0; q < 4; q++) acc[mt][nt][q] = 0.f;

    // ---- stage: copy chunk [kc, kc+32) into stage sb (hi cols 0-31, lo cols 32-63) ----
    auto stage = [&](int sb, int kc){
        uint32_t ub = usm + sb*STAGEB;
        #pragma unroll
        for (int i = tid; i < 512; i += 256) {       // A: 128 x 32
            int r = i >> 2, cc = (i & 3) * 8;
            int gr = row0 + r;
            int grc = gr < N ? gr : 0;
            int sz = gr < N ? 16 : 0;
            uint32_t d = ub + (uint32_t)(r*LDA + cc)*2;
            cpa16(d,      Ahi + (size_t)grc*K + kc + cc, sz);
            cpa16(d + 64, Alo + (size_t)grc*K + kc + cc, sz);
        }
        {                                            // W: 64 x 32 (one i per thread)
            int i = tid & 255;
            if (i < 256) {
                int r = i >> 2, cc = (i & 3) * 8;
                uint32_t d = ub + AOFFB + (uint32_t)(r*LDA + cc)*2;
                cpa16(d,      Whi + (size_t)(col0 + r)*K + kc + cc, 16);
                cpa16(d + 64, Wlo + (size_t)(col0 + r)*K + kc + cc, 16);
            }
        }
        asm volatile("cp.async.commit_group;");
    };

    stage(0, 0);
    int buf = 0;
    for (int kc = 0; kc < K; kc += 32) {
        if (kc + 32 < K) {
            stage(buf ^ 1, kc + 32);
            asm volatile("cp.async.wait_group 1;");
        } else {
            asm volatile("cp.async.wait_group 0;");
        }
        __syncthreads();

        uint32_t ub = usm + buf*STAGEB;
        uint32_t abase = ub + (uint32_t)(arow*LDA + acol)*2;
        uint32_t bbase = ub + AOFFB + (uint32_t)(brow*LDA + bcol)*2;

        // term offsets (bytes): (Ahi,Whi)=(0,0), (Ahi,Wlo)=(0,64), (Alo,Whi)=(64,0)
        const uint32_t aoffs[3] = {0u, 0u, 64u};
        const uint32_t boffs[3] = {0u, 64u, 0u};

        #pragma unroll
        for (int t = 0; t < 3; t++) {
            uint32_t ab = abase + aoffs[t];
            uint32_t bb = bbase + boffs[t];
            #pragma unroll
            for (int k0 = 0; k0 < 32; k0 += 16) {
                uint32_t af[2][4], bf[2][4];
                ldsm4(af[0], ab + k0*2);
                ldsm4(af[1], ab + (16*LDA + k0)*2);
                ldsm4(bf[0], bb + k0*2);
                ldsm4(bf[1], bb + (16*LDA + k0)*2);
                #pragma unroll
                for (int mt = 0; mt < 2; mt++) {
                    mma16816(acc[mt][0], af[mt], bf[0]);
                    mma16816(acc[mt][1], af[mt], bf[0] + 2);
                    mma16816(acc[mt][2], af[mt], bf[1]);
                    mma16816(acc[mt][3], af[mt], bf[1] + 2);
                }
            }
        }
        __syncthreads();
        buf ^= 1;
    }

    // ---- epilogue ----
    #pragma unroll
    for (int mt = 0; mt < 2; mt++) {
        int gr0 = row0 + wm*32 + mt*16 + gid;
        #pragma unroll
        for (int half = 0; half < 2; half++) {
            int r = gr0 + half*8;
            if (r >= N) continue;
            #pragma unroll
            for (int nt = 0; nt < 4; nt++) {
                int gc = col0 + wn*32 + nt*8 + tig*2;
                float v0 = acc[mt][nt][half*2+0];
                float v1 = acc[mt][nt][half*2+1];
                if (bias) { v0 += bias[gc]; v1 += bias[gc+1]; }
                if (act == 1) { v0 = leakyf(v0); v1 = leakyf(v1); }
                *(float2*)(C + (size_t)r*Ko + gc) = make_float2(v0, v1);
                if (Chi) {
                    bf16 h0 = __float2bfloat16(v0), h1 = __float2bfloat16(v1);
                    *(bf162*)(Chi + (size_t)r*Ko + gc) = __halves2bfloat162(h0, h1);
                    *(bf162*)(Clo + (size_t)r*Ko + gc) =
                        __halves2bfloat162(__float2bfloat16(v0 - __bfloat162float(h0)),
                                           __float2bfloat16(v1 - __bfloat162float(h1)));
                }
            }
        }
    }
}

// ---------------- small GEMM (graph-level, N<=1024): 64x64 tiles ----------------
__global__ void sgemm_bias_act(const float* __restrict__ A, const float* __restrict__ W,
                               const float* __restrict__ bias, float* __restrict__ C,
                               int N, int M, int ldw, int Ko, int act)
{
    __shared__ float sA[16][64];
    __shared__ float sB[16][64];
    const int tid = threadIdx.x;
    const int tx = tid & 15, ty = tid >> 4;
    const int row0 = blockIdx.y * 64;
    const int col0 = blockIdx.x * 64;

    float acc[4][4];
    #pragma unroll
    for (int i = 0; i < 4; i++)
        #pragma unroll
        for (int j = 0; j < 4; j++) acc[i][j] = 0.f;

    const int r  = tid >> 2;
    const int kq = (tid & 3) * 4;

    for (int k0 = 0; k0 < M; k0 += 16) {
        int gr = row0 + r;
        float4 av;
        if (gr < N) av = *(const float4*)(A + (size_t)gr*M + k0 + kq);
        else        av = make_float4(0.f,0.f,0.f,0.f);
        sA[kq+0][r]=av.x; sA[kq+1][r]=av.y; sA[kq+2][r]=av.z; sA[kq+3][r]=av.w;

        float4 bv = *(const float4*)(W + (size_t)(col0 + r)*ldw + k0 + kq);
        sB[kq+0][r]=bv.x; sB[kq+1][r]=bv.y; sB[kq+2][r]=bv.z; sB[kq+3][r]=bv.w;
        __syncthreads();

        #pragma unroll
        for (int kk = 0; kk < 16; kk++) {
            float ra[4], rb[4];
            #pragma unroll
            for (int i = 0; i < 4; i++) ra[i] = sA[kk][ty*4+i];
            #pragma unroll
            for (int j = 0; j < 4; j++) rb[j] = sB[kk][tx*4+j];
            #pragma unroll
            for (int i = 0; i < 4; i++)
                #pragma unroll
                for (int j = 0; j < 4; j++) acc[i][j] = fmaf(ra[i], rb[j], acc[i][j]);
        }
        __syncthreads();
    }

    #pragma unroll
    for (int i = 0; i < 4; i++) {
        int gr = row0 + ty*4 + i;
        if (gr >= N) continue;
        #pragma unroll
        for (int j = 0; j < 4; j++) {
            int gc = col0 + tx*4 + j;
            float v = acc[i][j];
            if (bias) v += bias[gc];
            if (act == 1) v = leakyf(v);
            C[(size_t)gr*Ko + gc] = v;
        }
    }
}

// ---------------- per-node dual dot ----------------
__global__ void rowdot2(const float* __restrict__ A, const float* __restrict__ v1,
                        const float* __restrict__ B, const float* __restrict__ v2,
                        float* __restrict__ o1, float* __restrict__ o2, int N)
{
    int gw = (blockIdx.x*blockDim.x + threadIdx.x) >> 5;
    int lane = threadIdx.x & 31;
    if (gw >= N) return;
    const float4 a = *(const float4*)(A + (size_t)gw*128 + lane*4);
    const float4 b = *(const float4*)(B + (size_t)gw*128 + lane*4);
    const float4 u = *(const float4*)(v1 + lane*4);
    const float4 w = *(const float4*)(v2 + lane*4);
    float s1 = a.x*u.x + a.y*u.y + a.z*u.z + a.w*u.w;
    float s2 = b.x*w.x + b.y*w.y + b.z*w.z + b.w*w.w;
    #pragma unroll
    for (int o = 16; o; o >>= 1) {
        s1 += __shfl_xor_sync(0xffffffffu, s1, o);
        s2 += __shfl_xor_sync(0xffffffffu, s2, o);
    }
    if (lane == 0) { o1[gw] = s1; if (o2) o2[gw] = s2; }
}

// ======================= CSR build =======================
__global__ void csr_zero()
{
    int i = blockIdx.x*blockDim.x + threadIdx.x;
    if (i < NN) { g_deg[i] = 0; g_cur[i] = 0; }
}

__global__ void csr_hist(const int* __restrict__ ei)
{
    int e = blockIdx.x*blockDim.x + threadIdx.x;
    if (e >= NE) return;
    atomicAdd(&g_deg[ei[NE+e]], 1);
}

__global__ void __launch_bounds__(1024) csr_scan()
{
    __shared__ int wsum[32];
    const int t = threadIdx.x, lane = t & 31, w = t >> 5;
    const int CH = (NN + 1023) / 1024;
    const int base = t*CH;
    const int end = min(base + CH, NN);
    int sum = 0;
    for (int i = base; i < end; i++) sum += g_deg[i];
    int v = sum;
    #pragma unroll
    for (int o = 1; o < 32; o <<= 1) {
        int u = __shfl_up_sync(0xffffffffu, v, o);
        if (lane >= o) v += u;
    }
    if (lane == 31) wsum[w] = v;
    __syncthreads();
    if (w == 0) {
        int s = wsum[lane];
        #pragma unroll
        for (int o = 1; o < 32; o <<= 1) {
            int u = __shfl_up_sync(0xffffffffu, s, o);
            if (lane >= o) s += u;
        }
        wsum[lane] = s;
    }
    __syncthreads();
    int off = v - sum + (w ? wsum[w-1] : 0);
    for (int i = base; i < end; i++) { g_rowptr[i] = off; off += g_deg[i]; }
    if (t == 1023) g_rowptr[NN] = NE;
}

__global__ void csr_fill(const int* __restrict__ ei)
{
    int e = blockIdx.x*blockDim.x + threadIdx.x;
    if (e >= NE) return;
    int d = ei[NE+e];
    int slot = atomicAdd(&g_cur[d], 1);
    g_csr[g_rowptr[d] + slot] = ei[e];
}

// =======================================================================
// Fused GAT aggregation: warp per dst node; unroll-2 edge loop.
// =======================================================================
__global__ void __launch_bounds__(256)
gat_agg(const float* __restrict__ as, const float* __restrict__ ad,
        const float* __restrict__ msg, const float* __restrict__ bias)
{
    int w = (blockIdx.x*blockDim.x + threadIdx.x) >> 5;
    int lane = threadIdx.x & 31;
    if (w >= NN) return;
    const int s = g_rowptr[w], e = g_rowptr[w+1];
    const float adv = ad[w];

    float mx = -3.402823e38f;
    for (int j = s + lane; j < e; j += 32)
        mx = fmaxf(mx, leakyf(as[g_csr[j]] + adv));
    #pragma unroll
    for (int o = 16; o; o >>= 1)
        mx = fmaxf(mx, __shfl_xor_sync(0xffffffffu, mx, o));

    float ssum = 0.f;
    float4 acc = make_float4(0.f,0.f,0.f,0.f);
    int j = s;
    for (; j + 1 < e; j += 2) {
        int s0 = g_csr[j], s1 = g_csr[j+1];
        float w0 = expf(leakyf(as[s0] + adv) - mx);
        float w1 = expf(leakyf(as[s1] + adv) - mx);
        ssum += w0 + w1;
        float4 m0 = *(const float4*)(msg + (size_t)s0*128 + lane*4);
        float4 m1 = *(const float4*)(msg + (size_t)s1*128 + lane*4);
        acc.x = fmaf(w0, m0.x, fmaf(w1, m1.x, acc.x));
        acc.y = fmaf(w0, m0.y, fmaf(w1, m1.y, acc.y));
        acc.z = fmaf(w0, m0.z, fmaf(w1, m1.z, acc.z));
        acc.w = fmaf(w0, m0.w, fmaf(w1, m1.w, acc.w));
    }
    if (j < e) {
        int s0 = g_csr[j];
        float w0 = expf(leakyf(as[s0] + adv) - mx);
        ssum += w0;
        float4 m0 = *(const float4*)(msg + (size_t)s0*128 + lane*4);
        acc.x = fmaf(w0, m0.x, acc.x);
        acc.y = fmaf(w0, m0.y, acc.y);
        acc.z = fmaf(w0, m0.z, acc.z);
        acc.w = fmaf(w0, m0.w, acc.w);
    }
    float inv = 1.f / (ssum + 1e-16f);
    float4 bv = *(const float4*)(bias + lane*4);
    float o0 = eluf(acc.x*inv + bv.x);
    float o1 = eluf(acc.y*inv + bv.y);
    float o2 = eluf(acc.z*inv + bv.z);
    float o3 = eluf(acc.w*inv + bv.w);

    size_t base = (size_t)w*128 + lane*4;
    bf16 h0 = __float2bfloat16(o0), h1 = __float2bfloat16(o1);
    bf16 h2 = __float2bfloat16(o2), h3 = __float2bfloat16(o3);
    *(bf162*)(g_hhi + base)     = __halves2bfloat162(h0, h1);
    *(bf162*)(g_hhi + base + 2) = __halves2bfloat162(h2, h3);
    *(bf162*)(g_hlo + base)     = __halves2bfloat162(__float2bfloat16(o0 - __bfloat162float(h0)),
                                                     __float2bfloat16(o1 - __bfloat162float(h1)));
    *(bf162*)(g_hlo + base + 2) = __halves2bfloat162(__float2bfloat16(o2 - __bfloat162float(h2)),
                                                     __float2bfloat16(o3 - __bfloat162float(h3)));
}

// ---------------- elementwise GRU: x_new = relu(gru); writes float + bf16 hi/lo ----
__global__ void gru_elem(const float* __restrict__ gi, const float* __restrict__ gh,
                         float* __restrict__ hstate, bf16* __restrict__ ohi,
                         bf16* __restrict__ olo, int rows)
{
    int i = blockIdx.x*blockDim.x + threadIdx.x;
    if (i >= rows*32) return;
    int n = i >> 5, q = (i & 31) * 4;
    const float* a = gi + (size_t)n*384 + q;
    const float* b = gh + (size_t)n*384 + q;
    float4 ai = *(const float4*)(a);
    float4 az = *(const float4*)(a + 128);
    float4 an = *(const float4*)(a + 256);
    float4 bi = *(const float4*)(b);
    float4 bz = *(const float4*)(b + 128);
    float4 bn = *(const float4*)(b + 256);
    float4 hv = *(float4*)(hstate + (size_t)n*128 + q);

    float r, z, nn, v;
    r = sigmf(ai.x + bi.x); z = sigmf(az.x + bz.x); nn = tanhf(an.x + r*bn.x);
    v = (1.f - z)*nn + z*hv.x; hv.x = v > 0.f ? v : 0.f;
    r = sigmf(ai.y + bi.y); z = sigmf(az.y + bz.y); nn = tanhf(an.y + r*bn.y);
    v = (1.f - z)*nn + z*hv.y; hv.y = v > 0.f ? v : 0.f;
    r = sigmf(ai.z + bi.z); z = sigmf(az.z + bz.z); nn = tanhf(an.z + r*bn.z);
    v = (1.f - z)*nn + z*hv.z; hv.z = v > 0.f ? v : 0.f;
    r = sigmf(ai.w + bi.w); z = sigmf(az.w + bz.w); nn = tanhf(an.w + r*bn.w);
    v = (1.f - z)*nn + z*hv.w; hv.w = v > 0.f ? v : 0.f;

    *(float4*)(hstate + (size_t)n*128 + q) = hv;

    if (ohi) {
        size_t base = (size_t)n*128 + q;
        bf16 h0 = __float2bfloat16(hv.x), h1 = __float2bfloat16(hv.y);
        bf16 h2 = __float2bfloat16(hv.z), h3 = __float2bfloat16(hv.w);
        *(bf162*)(ohi + base)     = __halves2bfloat162(h0, h1);
        *(bf162*)(ohi + base + 2) = __halves2bfloat162(h2, h3);
        *(bf162*)(olo + base)     = __halves2bfloat162(__float2bfloat16(hv.x - __bfloat162float(h0)),
                                                       __float2bfloat16(hv.y - __bfloat162float(h1)));
        *(bf162*)(olo + base + 2) = __halves2bfloat162(__float2bfloat16(hv.z - __bfloat162float(h2)),
                                                       __float2bfloat16(hv.w - __bfloat162float(h3)));
    }
}

// ---------------- GATE edge-MLP constant bias ----------------
__global__ void cbias_k(const float* __restrict__ Wg1)
{
    int k = threadIdx.x;
    float c = 0.f;
    for (int j = 128; j < 153; j++) c += Wg1[k*153 + j];
    g_cb[k] = c;
}

// ---------------- readout ----------------
__global__ void seg_offsets(const int* __restrict__ batch)
{
    int g = blockIdx.x*blockDim.x + threadIdx.x;
    if (g > NG) return;
    int lo = 0, hi = NN;
    while (lo < hi) { int mid = (lo+hi) >> 1; if (batch[mid] < g) lo = mid+1; else hi = mid; }
    g_off[g] = lo;
}

__global__ void readout_sum(const float* __restrict__ x)
{
    int g = blockIdx.x, k = threadIdx.x;
    int s = g_off[g], e = g_off[g+1];
    float acc = 0.f;
    for (int n = s; n < e; n++) acc += x[(size_t)n*128 + k];
    g_gout[g*128 + k] = acc > 0.f ? acc : 0.f;
}

__global__ void readout_attn(const float* __restrict__ asrc, const float* __restrict__ adst,
                             const float* __restrict__ xt, const float* __restrict__ bm)
{
    int g = blockIdx.x, tid = threadIdx.x;   // 128 threads
    int s = g_off[g], e = g_off[g+1];
    float ad = adst[g];
    __shared__ float red[4];

    float mx = -3.402823e38f;
    for (int n = s + tid; n < e; n += 128) mx = fmaxf(mx, leakyf(asrc[n] + ad));
    #pragma unroll
    for (int o = 16; o; o >>= 1) mx = fmaxf(mx, __shfl_xor_sync(0xffffffffu, mx, o));
    if ((tid & 31) == 0) red[tid >> 5] = mx;
    __syncthreads();
    mx = fmaxf(fmaxf(red[0], red[1]), fmaxf(red[2], red[3]));
    __syncthreads();

    float sm = 0.f;
    for (int n = s + tid; n < e; n += 128) {
        float ee = expf(leakyf(asrc[n] + ad) - mx);
        g_e[n] = ee;
        sm += ee;
    }
    #pragma unroll
    for (int o = 16; o; o >>= 1) sm += __shfl_xor_sync(0xffffffffu, sm, o);
    if ((tid & 31) == 0) red[tid >> 5] = sm;
    __syncthreads();
    sm = red[0] + red[1] + red[2] + red[3];
    float inv = 1.f / (sm + 1e-16f);

    float acc = 0.f;
    for (int n = s; n < e; n++) acc = fmaf(xt[(size_t)n*128 + tid], g_e[n], acc);
    g_ggh[g*128 + tid] = eluf(acc*inv + bm[tid]);
}

__global__ void final_out(const float* __restrict__ W2, const float* __restrict__ b2,
                          float* __restrict__ out)
{
    int g = blockIdx.x, tid = threadIdx.x;
    __shared__ float red[4];
    float s = g_gout[g*128 + tid] * W2[tid];
    #pragma unroll
    for (int o = 16; o; o >>= 1) s += __shfl_xor_sync(0xffffffffu, s, o);
    if ((tid & 31) == 0) red[tid >> 5] = s;
    __syncthreads();
    if (tid == 0) out[g] = red[0] + red[1] + red[2] + red[3] + b2[0];
}

// ---------------- host orchestration ----------------
extern "C" void kernel_launch(void* const* d_in, const int* in_sizes, int n_in,
                              void* d_out, int out_size)
{
    const float* x0    = (const float*)d_in[0];
    const int*   ei    = (const int*)  d_in[1];
    const int*   batch = (const int*)  d_in[2];
    const float* W1    = (const float*)d_in[3];
    const float* b1    = (const float*)d_in[4];
    const float* Wg1   = (const float*)d_in[5];
    const float* att_l = (const float*)d_in[6];
    const float* att_r = (const float*)d_in[7];
    const float* Wg2   = (const float*)d_in[8];
    const float* bg    = (const float*)d_in[9];
    const float* Wih0  = (const float*)d_in[10];
    const float* Whh0  = (const float*)d_in[11];
    const float* bih0  = (const float*)d_in[12];
    const float* bhh0  = (const float*)d_in[13];
    const float* Wa        = (const float*)d_in[14];
    const float* att_src_a = (const float*)d_in[15];
    const float* att_dst_a = (const float*)d_in[16];
    const float* ba        = (const float*)d_in[17];
    const float* Wih_a     = (const float*)d_in[18];
    const float* Whh_a     = (const float*)d_in[19];
    const float* bih_a     = (const float*)d_in[20];
    const float* bhh_a     = (const float*)d_in[21];
    const float* Wm        = (const float*)d_in[22];
    const float* att_src_m = (const float*)d_in[23];
    const float* att_dst_m = (const float*)d_in[24];
    const float* bm        = (const float*)d_in[25];
    const float* Wih_m     = (const float*)d_in[26];
    const float* Whh_m     = (const float*)d_in[27];
    const float* bih_m     = (const float*)d_in[28];
    const float* bhh_m     = (const float*)d_in[29];
    const float* W2        = (const float*)d_in[30];
    const float* b2        = (const float*)d_in[31];

    float *px,*py,*pz,*pt1,*pt2,*pts,*prs,*pcb;
    float *pgout,*pggh,*pgoy,*pgog1,*pgog2,*pgad;
    bf16 *p0hi,*p0lo,*pxhi,*pxlo,*phhi,*phlo,*pwhi,*pwlo;
    cudaGetSymbolAddress((void**)&px,  g_x);
    cudaGetSymbolAddress((void**)&py,  g_y);
    cudaGetSymbolAddress((void**)&pz,  g_z);
    cudaGetSymbolAddress((void**)&pt1, g_t1);
    cudaGetSymbolAddress((void**)&pt2, g_t2);
    cudaGetSymbolAddress((void**)&pts, g_ts);
    cudaGetSymbolAddress((void**)&prs, g_rs);
    cudaGetSymbolAddress((void**)&pcb, g_cb);
    cudaGetSymbolAddress((void**)&pgout, g_gout);
    cudaGetSymbolAddress((void**)&pggh,  g_ggh);
    cudaGetSymbolAddress((void**)&pgoy,  g_goy);
    cudaGetSymbolAddress((void**)&pgog1, g_gog1);
    cudaGetSymbolAddress((void**)&pgog2, g_gog2);
    cudaGetSymbolAddress((void**)&pgad,  g_gad);
    cudaGetSymbolAddress((void**)&p0hi, g_0hi);
    cudaGetSymbolAddress((void**)&p0lo, g_0lo);
    cudaGetSymbolAddress((void**)&pxhi, g_xhi);
    cudaGetSymbolAddress((void**)&pxlo, g_xlo);
    cudaGetSymbolAddress((void**)&phhi, g_hhi);
    cudaGetSymbolAddress((void**)&phlo, g_hlo);
    cudaGetSymbolAddress((void**)&pwhi, g_whi);
    cudaGetSymbolAddress((void**)&pwlo, g_wlo);

    static int smem_set = 0;
    if (!smem_set) {
        cudaFuncSetAttribute(hgemm_mma, cudaFuncAttributeMaxDynamicSharedMemorySize, MM_SMEM);
        smem_set = 1;
    }

    const int RB = (NN + 127) / 128;
    const int EB   = (NE + 255) / 256;
    const int NB4  = (NN*32 + 255) / 256;
    const int DWB  = (NN*32 + 255) / 256;
    const int DGB  = (NG*32 + 255) / 256;
    const int AGG  = (NN*32 + 255) / 256;

    WPtrs wp;
    wp.p[0]=W1; wp.p[1]=Wg1; wp.p[2]=Wg2; wp.p[3]=Wih0; wp.p[4]=Whh0;
    wp.p[5]=Wa; wp.p[6]=Wa+128*128; wp.p[7]=Wih_a; wp.p[8]=Wih_a+384*128;
    wp.p[9]=Whh_a; wp.p[10]=Whh_a+384*128; wp.p[11]=Wm;

    // ---- prologue (idx 3 = K=128 WG2 GEMM: lands in ncu profile slot) ----
    conv_weights<<<dim3(64, 12), 256>>>(wp);
    conv_act<<<(NN*32 + 255)/256, 256>>>(x0, p0hi, p0lo, NN*32);
    hgemm_mma<<<dim3(2, RB), 256, MM_SMEM>>>(p0hi, p0lo, pwhi+OFF_W1, pwlo+OFF_W1,
                                             b1, px, pxhi, pxlo, NN, 64, 128, 1);
    hgemm_mma<<<dim3(2, RB), 256, MM_SMEM>>>(pxhi, pxlo, pwhi+OFF_WG2, pwlo+OFF_WG2,
                                             nullptr, pz, nullptr, nullptr, NN, 128, 128, 0);
    cbias_k<<<1, 128>>>(Wg1);
    csr_zero<<<(NN + 255)/256, 256>>>();
    csr_hist<<<EB, 256>>>(ei);
    csr_scan<<<1, 1024>>>();
    csr_fill<<<EB, 256>>>(ei);

    // ---- GATEConv ----
    hgemm_mma<<<dim3(2, RB), 256, MM_SMEM>>>(pxhi, pxlo, pwhi+OFF_WG1, pwlo+OFF_WG1,
                                             pcb, py, nullptr, nullptr, NN, 128, 128, 1);
    rowdot2<<<DWB, 256>>>(py, att_l, px, att_r, pts, prs, NN);
    gat_agg<<<AGG, 256>>>(pts, prs, pz, bg);
    hgemm_mma<<<dim3(6, RB), 256, MM_SMEM>>>(phhi, phlo, pwhi+OFF_WIH0, pwlo+OFF_WIH0,
                                             bih0, pt1, nullptr, nullptr, NN, 128, 384, 0);
    hgemm_mma<<<dim3(6, RB), 256, MM_SMEM>>>(pxhi, pxlo, pwhi+OFF_WHH0, pwlo+OFF_WHH0,
                                             bhh0, pt2, nullptr, nullptr, NN, 128, 384, 0);
    gru_elem<<<NB4, 256>>>(pt1, pt2, px, pxhi, pxlo, NN);

    // ---- 2 GATConv layers ----
    for (int l = 0; l < 2; l++) {
        hgemm_mma<<<dim3(2, RB), 256, MM_SMEM>>>(pxhi, pxlo,
                                                 pwhi+OFF_WA+l*16384, pwlo+OFF_WA+l*16384,
                                                 nullptr, pz, nullptr, nullptr, NN, 128, 128, 0);
        rowdot2<<<DWB, 256>>>(pz, att_src_a + l*128, pz, att_dst_a + l*128, pts, prs, NN);
        gat_agg<<<AGG, 256>>>(pts, prs, pz, ba + l*128);
        hgemm_mma<<<dim3(6, RB), 256, MM_SMEM>>>(phhi, phlo,
                                                 pwhi+OFF_WIHA+l*49152, pwlo+OFF_WIHA+l*49152,
                                                 bih_a + l*384, pt1, nullptr, nullptr, NN, 128, 384, 0);
        hgemm_mma<<<dim3(6, RB), 256, MM_SMEM>>>(pxhi, pxlo,
                                                 pwhi+OFF_WHHA+l*49152, pwlo+OFF_WHHA+l*49152,
                                                 bhh_a + l*384, pt2, nullptr, nullptr, NN, 128, 384, 0);
        gru_elem<<<NB4, 256>>>(pt1, pt2, px, pxhi, pxlo, NN);
    }

    // ---- attentive readout ----
    seg_offsets<<<5, 256>>>(batch);
    readout_sum<<<NG, 128>>>(px);
    hgemm_mma<<<dim3(2, RB), 256, MM_SMEM>>>(pxhi, pxlo, pwhi+OFF_WM, pwlo+OFF_WM,
                                             nullptr, pz, nullptr, nullptr, NN, 128, 128, 0);
    rowdot2<<<DWB, 256>>>(pz, att_src_m, pz, att_src_m, pts, nullptr, NN);

    for (int t = 0; t < 3; t++) {
        sgemm_bias_act<<<dim3(2, 16), 256>>>(pgout, Wm, nullptr, pgoy, NG, 128, 128, 128, 0);
        rowdot2<<<DGB, 256>>>(pgoy, att_dst_m, pgoy, att_dst_m, pgad, nullptr, NG);
        readout_attn<<<NG, 128>>>(pts, pgad, pz, bm);
        sgemm_bias_act<<<dim3(6, 16), 256>>>(pggh,  Wih_m, bih_m, pgog1, NG, 128, 128, 384, 0);
        sgemm_bias_act<<<dim3(6, 16), 256>>>(pgout, Whh_m, bhh_m, pgog2, NG, 128, 128, 384, 0);
        gru_elem<<<(NG*32 + 255)/256, 256>>>(pgog1, pgog2, pgout, nullptr, nullptr, NG);
    }

    final_out<<<NG, 128>>>(W2, b2, (float*)d_out);
}

// round 13
// speedup vs baseline: 1.2455x; 1.2455x over previous
#include <cuda_runtime.h>
#include <cuda_bf16.h>
#include <cstdint>
#include <math.h>

#define NN 50000
#define NE 800000
#define NG 1024

typedef __nv_bfloat16 bf16;
typedef __nv_bfloat162 bf162;

// ---------------- scratch (device globals; no allocation allowed) ----------------
__device__ float g_x [NN*128];
__device__ float g_y [NN*128];
__device__ float g_z [NN*128];
__device__ float g_t1[NN*384];
__device__ float g_t2[NN*384];
__device__ float g_ts[NN];
__device__ float g_rs[NN];
__device__ float g_e [NE];
__device__ int   g_deg[NN];
__device__ int   g_cur[NN];
__device__ int   g_rowptr[NN+1];
__device__ int   g_csr[NE];
__device__ int   g_off[NG+1];
__device__ float g_cb[128];
__device__ float g_gout[NG*128];
__device__ float g_ggh [NG*128];
__device__ float g_goy [NG*128];
__device__ float g_gog1[NG*384];
__device__ float g_gog2[NG*384];
__device__ float g_gad [NG];

// bf16 hi/lo activation buffers
__device__ __align__(16) bf16 g_0hi[NN*64];
__device__ __align__(16) bf16 g_0lo[NN*64];
__device__ __align__(16) bf16 g_xhi[NN*128];
__device__ __align__(16) bf16 g_xlo[NN*128];
__device__ __align__(16) bf16 g_hhi[NN*128];
__device__ __align__(16) bf16 g_hlo[NN*128];

// bf16 hi/lo weight scratch (packed, ld = K)
#define OFF_W1    0
#define OFF_WG1   8192
#define OFF_WG2   24576
#define OFF_WIH0  40960
#define OFF_WHH0  90112
#define OFF_WA    139264
#define OFF_WIHA  172032
#define OFF_WHHA  270336
#define OFF_WM    368640
#define W_TOTAL   385024
__device__ __align__(16) bf16 g_whi[W_TOTAL];
__device__ __align__(16) bf16 g_wlo[W_TOTAL];

// ---------------- helpers ----------------
__device__ __forceinline__ float leakyf(float v){ return v >= 0.f ? v : 0.01f*v; }
__device__ __forceinline__ float sigmf (float v){ return 1.f/(1.f+expf(-v)); }
__device__ __forceinline__ float eluf  (float v){ return v > 0.f ? v : (expf(v)-1.f); }

// =======================================================================
// weight conversion: all 12 node-GEMM weights -> packed bf16 hi/lo
// =======================================================================
struct WPtrs { const float* p[12]; };

__global__ void conv_weights(WPtrs wp)
{
    const int rows[12] = {128,128,128,384,384,128,128,384,384,384,384,128};
    const int cols[12] = { 64,128,128,128,128,128,128,128,128,128,128,128};
    const int ldws[12] = { 64,153,128,128,128,128,128,128,128,128,128,128};
    const int offs[12] = {OFF_W1,OFF_WG1,OFF_WG2,OFF_WIH0,OFF_WHH0,
                          OFF_WA,OFF_WA+16384,OFF_WIHA,OFF_WIHA+49152,
                          OFF_WHHA,OFF_WHHA+49152,OFF_WM};
    int s = blockIdx.y;
    const float* src = wp.p[s];
    int n = rows[s]*cols[s];
    for (int i = blockIdx.x*blockDim.x + threadIdx.x; i < n; i += gridDim.x*blockDim.x) {
        int r = i / cols[s], c = i - r*cols[s];
        float v = src[(size_t)r*ldws[s] + c];
        bf16 h = __float2bfloat16(v);
        g_whi[offs[s] + i] = h;
        g_wlo[offs[s] + i] = __float2bfloat16(v - __bfloat162float(h));
    }
}

__global__ void conv_act(const float* __restrict__ src, bf16* __restrict__ hi,
                         bf16* __restrict__ lo, int n2)
{
    int i = blockIdx.x*blockDim.x + threadIdx.x;
    if (i >= n2) return;
    float2 v = *(const float2*)(src + i*2);
    bf16 hx = __float2bfloat16(v.x), hy = __float2bfloat16(v.y);
    *(bf162*)(hi + i*2) = __halves2bfloat162(hx, hy);
    *(bf162*)(lo + i*2) = __halves2bfloat162(__float2bfloat16(v.x - __bfloat162float(hx)),
                                             __float2bfloat16(v.y - __bfloat162float(hy)));
}

// =======================================================================
// bf16 split-precision tensor-core GEMM body (R11 structure: BK=64,
// monolithic cp.async staging, separate hi/lo buffers, 55296B smem).
//   D = Ahi*Whi + Ahi*Wlo + Alo*Whi
// =======================================================================
#define LDA 72
#define ABUF (128*LDA)
#define WBUF (64*LDA)
#define MM_SMEM ((2*ABUF + 2*WBUF)*2)   // 55296 bytes

__device__ __forceinline__ void mma16816(float* c, const uint32_t* a, const uint32_t* b){
    asm volatile(
        "mma.sync.aligned.m16n8k16.row.col.f32.bf16.bf16.f32 "
        "{%0,%1,%2,%3}, {%4,%5,%6,%7}, {%8,%9}, {%0,%1,%2,%3};\n"
        : "+f"(c[0]), "+f"(c[1]), "+f"(c[2]), "+f"(c[3])
        : "r"(a[0]), "r"(a[1]), "r"(a[2]), "r"(a[3]), "r"(b[0]), "r"(b[1]));
}
__device__ __forceinline__ void ldsm4(uint32_t* r, uint32_t addr){
    asm volatile("ldmatrix.sync.aligned.m8n8.x4.shared.b16 {%0,%1,%2,%3}, [%4];"
        : "=r"(r[0]), "=r"(r[1]), "=r"(r[2]), "=r"(r[3]) : "r"(addr));
}
__device__ __forceinline__ void cpa16(uint32_t dst, const void* src, int sz){
    asm volatile("cp.async.cg.shared.global [%0], [%1], 16, %2;"
        :: "r"(dst), "l"(src), "r"(sz));
}

__device__ __forceinline__ void gemm_body(
    const bf16* __restrict__ Ahi, const bf16* __restrict__ Alo,
    const bf16* __restrict__ Whi, const bf16* __restrict__ Wlo,
    const float* __restrict__ bias, float* __restrict__ C,
    bf16* __restrict__ Chi, bf16* __restrict__ Clo,
    int N, int K, int Ko, int act, int row0, int col0, bf16* sm)
{
    bf16* sAhi = sm;
    bf16* sAlo = sm + ABUF;
    bf16* sBhi = sm + 2*ABUF;
    bf16* sBlo = sm + 2*ABUF + WBUF;

    const int tid  = threadIdx.x;
    const int wid  = tid >> 5, lane = tid & 31;
    const int wm   = wid & 3,  wn   = wid >> 2;
    const int gid  = lane >> 2, tig = lane & 3;

    const int arow = wm*32 + (lane & 15);
    const int acol = (lane >> 4) << 3;
    const int brow = wn*32 + ((lane >> 4) << 3) + (lane & 7);
    const int bcol = ((lane >> 3) & 1) << 3;

    const uint32_t uAhi = (uint32_t)__cvta_generic_to_shared(sAhi);
    const uint32_t uAlo = (uint32_t)__cvta_generic_to_shared(sAlo);
    const uint32_t uBhi = (uint32_t)__cvta_generic_to_shared(sBhi);
    const uint32_t uBlo = (uint32_t)__cvta_generic_to_shared(sBlo);

    float acc[2][4][4];
    #pragma unroll
    for (int mt = 0; mt < 2; mt++)
        #pragma unroll
        for (int nt = 0; nt < 4; nt++)
            #pragma unroll
            for (int q = 0; q < 4; q++) acc[mt][nt][q] = 0.f;

    for (int kc = 0; kc < K; kc += 64) {
        #pragma unroll
        for (int i = tid; i < 1024; i += 256) {
            int r = i >> 3, cc = (i & 7) * 8;
            int gr = row0 + r;
            int grc = gr < N ? gr : 0;
            int sz = gr < N ? 16 : 0;
            uint32_t d = (uint32_t)(r*LDA + cc)*2;
            cpa16(uAhi + d, Ahi + (size_t)grc*K + kc + cc, sz);
            cpa16(uAlo + d, Alo + (size_t)grc*K + kc + cc, sz);
        }
        #pragma unroll
        for (int i = tid; i < 512; i += 256) {
            int r = i >> 3, cc = (i & 7) * 8;
            uint32_t d = (uint32_t)(r*LDA + cc)*2;
            cpa16(uBhi + d, Whi + (size_t)(col0 + r)*K + kc + cc, 16);
            cpa16(uBlo + d, Wlo + (size_t)(col0 + r)*K + kc + cc, 16);
        }
        asm volatile("cp.async.commit_group;");
        asm volatile("cp.async.wait_group 0;");
        __syncthreads();

        const uint32_t At[3] = { uAhi, uAhi, uAlo };
        const uint32_t Bt[3] = { uBhi, uBlo, uBhi };

        #pragma unroll 1
        for (int t = 0; t < 3; t++) {
            uint32_t abase = At[t] + (uint32_t)(arow*LDA + acol)*2;
            uint32_t bbase = Bt[t] + (uint32_t)(brow*LDA + bcol)*2;
            #pragma unroll
            for (int k0 = 0; k0 < 64; k0 += 16) {
                uint32_t af[2][4], bf[2][4];
                ldsm4(af[0], abase + k0*2);
                ldsm4(af[1], abase + (16*LDA + k0)*2);
                ldsm4(bf[0], bbase + k0*2);
                ldsm4(bf[1], bbase + (16*LDA + k0)*2);
                #pragma unroll
                for (int mt = 0; mt < 2; mt++) {
                    mma16816(acc[mt][0], af[mt], bf[0]);
                    mma16816(acc[mt][1], af[mt], bf[0] + 2);
                    mma16816(acc[mt][2], af[mt], bf[1]);
                    mma16816(acc[mt][3], af[mt], bf[1] + 2);
                }
            }
        }
        __syncthreads();
    }

    #pragma unroll
    for (int mt = 0; mt < 2; mt++) {
        int gr0 = row0 + wm*32 + mt*16 + gid;
        #pragma unroll
        for (int half = 0; half < 2; half++) {
            int r = gr0 + half*8;
            if (r >= N) continue;
            #pragma unroll
            for (int nt = 0; nt < 4; nt++) {
                int gc = col0 + wn*32 + nt*8 + tig*2;
                float v0 = acc[mt][nt][half*2+0];
                float v1 = acc[mt][nt][half*2+1];
                if (bias) { v0 += bias[gc]; v1 += bias[gc+1]; }
                if (act == 1) { v0 = leakyf(v0); v1 = leakyf(v1); }
                *(float2*)(C + (size_t)r*Ko + gc) = make_float2(v0, v1);
                if (Chi) {
                    bf16 h0 = __float2bfloat16(v0), h1 = __float2bfloat16(v1);
                    *(bf162*)(Chi + (size_t)r*Ko + gc) = __halves2bfloat162(h0, h1);
                    *(bf162*)(Clo + (size_t)r*Ko + gc) =
                        __halves2bfloat162(__float2bfloat16(v0 - __bfloat162float(h0)),
                                           __float2bfloat16(v1 - __bfloat162float(h1)));
                }
            }
        }
    }
}

__global__ void __launch_bounds__(256, 4)
hgemm_mma(const bf16* __restrict__ Ahi, const bf16* __restrict__ Alo,
          const bf16* __restrict__ Whi, const bf16* __restrict__ Wlo,
          const float* __restrict__ bias, float* __restrict__ C,
          bf16* __restrict__ Chi, bf16* __restrict__ Clo,
          int N, int K, int Ko, int act)
{
    extern __shared__ bf16 sm[];
    gemm_body(Ahi, Alo, Whi, Wlo, bias, C, Chi, Clo, N, K, Ko, act,
              blockIdx.y*128, blockIdx.x*64, sm);
}

// merged GRU pair: blockIdx.x<6 -> set0 (gi), else set1 (gh). Ko=384, K=128.
struct GSet { const bf16 *Ahi, *Alo, *Whi, *Wlo; const float* bias; float* C; };

__global__ void __launch_bounds__(256, 4)
hgemm_dual(GSet s0, GSet s1, int N)
{
    extern __shared__ bf16 sm[];
    bool second = blockIdx.x >= 6;
    const GSet& s = second ? s1 : s0;
    int col0 = (blockIdx.x - (second ? 6 : 0)) * 64;
    gemm_body(s.Ahi, s.Alo, s.Whi, s.Wlo, s.bias, s.C, nullptr, nullptr,
              N, 128, 384, 0, blockIdx.y*128, col0, sm);
}

// ---------------- small GEMM (graph-level, N<=1024): 64x64 tiles ----------------
__global__ void sgemm_bias_act(const float* __restrict__ A, const float* __restrict__ W,
                               const float* __restrict__ bias, float* __restrict__ C,
                               int N, int M, int ldw, int Ko, int act)
{
    __shared__ float sA[16][64];
    __shared__ float sB[16][64];
    const int tid = threadIdx.x;
    const int tx = tid & 15, ty = tid >> 4;
    const int row0 = blockIdx.y * 64;
    const int col0 = blockIdx.x * 64;

    float acc[4][4];
    #pragma unroll
    for (int i = 0; i < 4; i++)
        #pragma unroll
        for (int j = 0; j < 4; j++) acc[i][j] = 0.f;

    const int r  = tid >> 2;
    const int kq = (tid & 3) * 4;

    for (int k0 = 0; k0 < M; k0 += 16) {
        int gr = row0 + r;
        float4 av;
        if (gr < N) av = *(const float4*)(A + (size_t)gr*M + k0 + kq);
        else        av = make_float4(0.f,0.f,0.f,0.f);
        sA[kq+0][r]=av.x; sA[kq+1][r]=av.y; sA[kq+2][r]=av.z; sA[kq+3][r]=av.w;

        float4 bv = *(const float4*)(W + (size_t)(col0 + r)*ldw + k0 + kq);
        sB[kq+0][r]=bv.x; sB[kq+1][r]=bv.y; sB[kq+2][r]=bv.z; sB[kq+3][r]=bv.w;
        __syncthreads();

        #pragma unroll
        for (int kk = 0; kk < 16; kk++) {
            float ra[4], rb[4];
            #pragma unroll
            for (int i = 0; i < 4; i++) ra[i] = sA[kk][ty*4+i];
            #pragma unroll
            for (int j = 0; j < 4; j++) rb[j] = sB[kk][tx*4+j];
            #pragma unroll
            for (int i = 0; i < 4; i++)
                #pragma unroll
                for (int j = 0; j < 4; j++) acc[i][j] = fmaf(ra[i], rb[j], acc[i][j]);
        }
        __syncthreads();
    }

    #pragma unroll
    for (int i = 0; i < 4; i++) {
        int gr = row0 + ty*4 + i;
        if (gr >= N) continue;
        #pragma unroll
        for (int j = 0; j < 4; j++) {
            int gc = col0 + tx*4 + j;
            float v = acc[i][j];
            if (bias) v += bias[gc];
            if (act == 1) v = leakyf(v);
            C[(size_t)gr*Ko + gc] = v;
        }
    }
}

// ---------------- per-node dual dot ----------------
__global__ void rowdot2(const float* __restrict__ A, const float* __restrict__ v1,
                        const float* __restrict__ B, const float* __restrict__ v2,
                        float* __restrict__ o1, float* __restrict__ o2, int N)
{
    int gw = (blockIdx.x*blockDim.x + threadIdx.x) >> 5;
    int lane = threadIdx.x & 31;
    if (gw >= N) return;
    const float4 a = *(const float4*)(A + (size_t)gw*128 + lane*4);
    const float4 b = *(const float4*)(B + (size_t)gw*128 + lane*4);
    const float4 u = *(const float4*)(v1 + lane*4);
    const float4 w = *(const float4*)(v2 + lane*4);
    float s1 = a.x*u.x + a.y*u.y + a.z*u.z + a.w*u.w;
    float s2 = b.x*w.x + b.y*w.y + b.z*w.z + b.w*w.w;
    #pragma unroll
    for (int o = 16; o; o >>= 1) {
        s1 += __shfl_xor_sync(0xffffffffu, s1, o);
        s2 += __shfl_xor_sync(0xffffffffu, s2, o);
    }
    if (lane == 0) { o1[gw] = s1; if (o2) o2[gw] = s2; }
}

// ======================= CSR build =======================
__global__ void csr_zero()
{
    int i = blockIdx.x*blockDim.x + threadIdx.x;
    if (i < NN) { g_deg[i] = 0; g_cur[i] = 0; }
}

__global__ void csr_hist(const int* __restrict__ ei)
{
    int e = blockIdx.x*blockDim.x + threadIdx.x;
    if (e >= NE) return;
    atomicAdd(&g_deg[ei[NE+e]], 1);
}

__global__ void __launch_bounds__(1024) csr_scan()
{
    __shared__ int wsum[32];
    const int t = threadIdx.x, lane = t & 31, w = t >> 5;
    const int CH = (NN + 1023) / 1024;
    const int base = t*CH;
    const int end = min(base + CH, NN);
    int sum = 0;
    for (int i = base; i < end; i++) sum += g_deg[i];
    int v = sum;
    #pragma unroll
    for (int o = 1; o < 32; o <<= 1) {
        int u = __shfl_up_sync(0xffffffffu, v, o);
        if (lane >= o) v += u;
    }
    if (lane == 31) wsum[w] = v;
    __syncthreads();
    if (w == 0) {
        int s = wsum[lane];
        #pragma unroll
        for (int o = 1; o < 32; o <<= 1) {
            int u = __shfl_up_sync(0xffffffffu, s, o);
            if (lane >= o) s += u;
        }
        wsum[lane] = s;
    }
    __syncthreads();
    int off = v - sum + (w ? wsum[w-1] : 0);
    for (int i = base; i < end; i++) { g_rowptr[i] = off; off += g_deg[i]; }
    if (t == 1023) g_rowptr[NN] = NE;
}

__global__ void csr_fill(const int* __restrict__ ei)
{
    int e = blockIdx.x*blockDim.x + threadIdx.x;
    if (e >= NE) return;
    int d = ei[NE+e];
    int slot = atomicAdd(&g_cur[d], 1);
    g_csr[g_rowptr[d] + slot] = ei[e];
}

// =======================================================================
// Fused GAT aggregation: warp per dst node; unroll-2 edge loop.
// =======================================================================
__global__ void __launch_bounds__(256)
gat_agg(const float* __restrict__ as, const float* __restrict__ ad,
        const float* __restrict__ msg, const float* __restrict__ bias)
{
    int w = (blockIdx.x*blockDim.x + threadIdx.x) >> 5;
    int lane = threadIdx.x & 31;
    if (w >= NN) return;
    const int s = g_rowptr[w], e = g_rowptr[w+1];
    const float adv = ad[w];

    float mx = -3.402823e38f;
    for (int j = s + lane; j < e; j += 32)
        mx = fmaxf(mx, leakyf(as[g_csr[j]] + adv));
    #pragma unroll
    for (int o = 16; o; o >>= 1)
        mx = fmaxf(mx, __shfl_xor_sync(0xffffffffu, mx, o));

    float ssum = 0.f;
    float4 acc = make_float4(0.f,0.f,0.f,0.f);
    int j = s;
    for (; j + 1 < e; j += 2) {
        int s0 = g_csr[j], s1 = g_csr[j+1];
        float w0 = expf(leakyf(as[s0] + adv) - mx);
        float w1 = expf(leakyf(as[s1] + adv) - mx);
        ssum += w0 + w1;
        float4 m0 = *(const float4*)(msg + (size_t)s0*128 + lane*4);
        float4 m1 = *(const float4*)(msg + (size_t)s1*128 + lane*4);
        acc.x = fmaf(w0, m0.x, fmaf(w1, m1.x, acc.x));
        acc.y = fmaf(w0, m0.y, fmaf(w1, m1.y, acc.y));
        acc.z = fmaf(w0, m0.z, fmaf(w1, m1.z, acc.z));
        acc.w = fmaf(w0, m0.w, fmaf(w1, m1.w, acc.w));
    }
    if (j < e) {
        int s0 = g_csr[j];
        float w0 = expf(leakyf(as[s0] + adv) - mx);
        ssum += w0;
        float4 m0 = *(const float4*)(msg + (size_t)s0*128 + lane*4);
        acc.x = fmaf(w0, m0.x, acc.x);
        acc.y = fmaf(w0, m0.y, acc.y);
        acc.z = fmaf(w0, m0.z, acc.z);
        acc.w = fmaf(w0, m0.w, acc.w);
    }
    float inv = 1.f / (ssum + 1e-16f);
    float4 bv = *(const float4*)(bias + lane*4);
    float o0 = eluf(acc.x*inv + bv.x);
    float o1 = eluf(acc.y*inv + bv.y);
    float o2 = eluf(acc.z*inv + bv.z);
    float o3 = eluf(acc.w*inv + bv.w);

    size_t base = (size_t)w*128 + lane*4;
    bf16 h0 = __float2bfloat16(o0), h1 = __float2bfloat16(o1);
    bf16 h2 = __float2bfloat16(o2), h3 = __float2bfloat16(o3);
    *(bf162*)(g_hhi + base)     = __halves2bfloat162(h0, h1);
    *(bf162*)(g_hhi + base + 2) = __halves2bfloat162(h2, h3);
    *(bf162*)(g_hlo + base)     = __halves2bfloat162(__float2bfloat16(o0 - __bfloat162float(h0)),
                                                     __float2bfloat16(o1 - __bfloat162float(h1)));
    *(bf162*)(g_hlo + base + 2) = __halves2bfloat162(__float2bfloat16(o2 - __bfloat162float(h2)),
                                                     __float2bfloat16(o3 - __bfloat162float(h3)));
}

// ---------------- elementwise GRU: x_new = relu(gru); writes float + bf16 hi/lo ----
__global__ void gru_elem(const float* __restrict__ gi, const float* __restrict__ gh,
                         float* __restrict__ hstate, bf16* __restrict__ ohi,
                         bf16* __restrict__ olo, int rows)
{
    int i = blockIdx.x*blockDim.x + threadIdx.x;
    if (i >= rows*32) return;
    int n = i >> 5, q = (i & 31) * 4;
    const float* a = gi + (size_t)n*384 + q;
    const float* b = gh + (size_t)n*384 + q;
    float4 ai = *(const float4*)(a);
    float4 az = *(const float4*)(a + 128);
    float4 an = *(const float4*)(a + 256);
    float4 bi = *(const float4*)(b);
    float4 bz = *(const float4*)(b + 128);
    float4 bn = *(const float4*)(b + 256);
    float4 hv = *(float4*)(hstate + (size_t)n*128 + q);

    float r, z, nn, v;
    r = sigmf(ai.x + bi.x); z = sigmf(az.x + bz.x); nn = tanhf(an.x + r*bn.x);
    v = (1.f - z)*nn + z*hv.x; hv.x = v > 0.f ? v : 0.f;
    r = sigmf(ai.y + bi.y); z = sigmf(az.y + bz.y); nn = tanhf(an.y + r*bn.y);
    v = (1.f - z)*nn + z*hv.y; hv.y = v > 0.f ? v : 0.f;
    r = sigmf(ai.z + bi.z); z = sigmf(az.z + bz.z); nn = tanhf(an.z + r*bn.z);
    v = (1.f - z)*nn + z*hv.z; hv.z = v > 0.f ? v : 0.f;
    r = sigmf(ai.w + bi.w); z = sigmf(az.w + bz.w); nn = tanhf(an.w + r*bn.w);
    v = (1.f - z)*nn + z*hv.w; hv.w = v > 0.f ? v : 0.f;

    *(float4*)(hstate + (size_t)n*128 + q) = hv;

    if (ohi) {
        size_t base = (size_t)n*128 + q;
        bf16 h0 = __float2bfloat16(hv.x), h1 = __float2bfloat16(hv.y);
        bf16 h2 = __float2bfloat16(hv.z), h3 = __float2bfloat16(hv.w);
        *(bf162*)(ohi + base)     = __halves2bfloat162(h0, h1);
        *(bf162*)(ohi + base + 2) = __halves2bfloat162(h2, h3);
        *(bf162*)(olo + base)     = __halves2bfloat162(__float2bfloat16(hv.x - __bfloat162float(h0)),
                                                       __float2bfloat16(hv.y - __bfloat162float(h1)));
        *(bf162*)(olo + base + 2) = __halves2bfloat162(__float2bfloat16(hv.z - __bfloat162float(h2)),
                                                       __float2bfloat16(hv.w - __bfloat162float(h3)));
    }
}

// ---------------- GATE edge-MLP constant bias ----------------
__global__ void cbias_k(const float* __restrict__ Wg1)
{
    int k = threadIdx.x;
    float c = 0.f;
    for (int j = 128; j < 153; j++) c += Wg1[k*153 + j];
    g_cb[k] = c;
}

// ---------------- readout ----------------
__global__ void seg_offsets(const int* __restrict__ batch)
{
    int g = blockIdx.x*blockDim.x + threadIdx.x;
    if (g > NG) return;
    int lo = 0, hi = NN;
    while (lo < hi) { int mid = (lo+hi) >> 1; if (batch[mid] < g) lo = mid+1; else hi = mid; }
    g_off[g] = lo;
}

__global__ void readout_sum(const float* __restrict__ x)
{
    int g = blockIdx.x, k = threadIdx.x;
    int s = g_off[g], e = g_off[g+1];
    float acc = 0.f;
    for (int n = s; n < e; n++) acc += x[(size_t)n*128 + k];
    g_gout[g*128 + k] = acc > 0.f ? acc : 0.f;
}

__global__ void readout_attn(const float* __restrict__ asrc, const float* __restrict__ adst,
                             const float* __restrict__ xt, const float* __restrict__ bm)
{
    int g = blockIdx.x, tid = threadIdx.x;   // 128 threads
    int s = g_off[g], e = g_off[g+1];
    float ad = adst[g];
    __shared__ float red[4];

    float mx = -3.402823e38f;
    for (int n = s + tid; n < e; n += 128) mx = fmaxf(mx, leakyf(asrc[n] + ad));
    #pragma unroll
    for (int o = 16; o; o >>= 1) mx = fmaxf(mx, __shfl_xor_sync(0xffffffffu, mx, o));
    if ((tid & 31) == 0) red[tid >> 5] = mx;
    __syncthreads();
    mx = fmaxf(fmaxf(red[0], red[1]), fmaxf(red[2], red[3]));
    __syncthreads();

    float sm = 0.f;
    for (int n = s + tid; n < e; n += 128) {
        float ee = expf(leakyf(asrc[n] + ad) - mx);
        g_e[n] = ee;
        sm += ee;
    }
    #pragma unroll
    for (int o = 16; o; o >>= 1) sm += __shfl_xor_sync(0xffffffffu, sm, o);
    if ((tid & 31) == 0) red[tid >> 5] = sm;
    __syncthreads();
    sm = red[0] + red[1] + red[2] + red[3];
    float inv = 1.f / (sm + 1e-16f);

    float acc = 0.f;
    for (int n = s; n < e; n++) acc = fmaf(xt[(size_t)n*128 + tid], g_e[n], acc);
    g_ggh[g*128 + tid] = eluf(acc*inv + bm[tid]);
}

__global__ void final_out(const float* __restrict__ W2, const float* __restrict__ b2,
                          float* __restrict__ out)
{
    int g = blockIdx.x, tid = threadIdx.x;
    __shared__ float red[4];
    float s = g_gout[g*128 + tid] * W2[tid];
    #pragma unroll
    for (int o = 16; o; o >>= 1) s += __shfl_xor_sync(0xffffffffu, s, o);
    if ((tid & 31) == 0) red[tid >> 5] = s;
    __syncthreads();
    if (tid == 0) out[g] = red[0] + red[1] + red[2] + red[3] + b2[0];
}

// ---------------- host orchestration ----------------
extern "C" void kernel_launch(void* const* d_in, const int* in_sizes, int n_in,
                              void* d_out, int out_size)
{
    const float* x0    = (const float*)d_in[0];
    const int*   ei    = (const int*)  d_in[1];
    const int*   batch = (const int*)  d_in[2];
    const float* W1    = (const float*)d_in[3];
    const float* b1    = (const float*)d_in[4];
    const float* Wg1   = (const float*)d_in[5];
    const float* att_l = (const float*)d_in[6];
    const float* att_r = (const float*)d_in[7];
    const float* Wg2   = (const float*)d_in[8];
    const float* bg    = (const float*)d_in[9];
    const float* Wih0  = (const float*)d_in[10];
    const float* Whh0  = (const float*)d_in[11];
    const float* bih0  = (const float*)d_in[12];
    const float* bhh0  = (const float*)d_in[13];
    const float* Wa        = (const float*)d_in[14];
    const float* att_src_a = (const float*)d_in[15];
    const float* att_dst_a = (const float*)d_in[16];
    const float* ba        = (const float*)d_in[17];
    const float* Wih_a     = (const float*)d_in[18];
    const float* Whh_a     = (const float*)d_in[19];
    const float* bih_a     = (const float*)d_in[20];
    const float* bhh_a     = (const float*)d_in[21];
    const float* Wm        = (const float*)d_in[22];
    const float* att_src_m = (const float*)d_in[23];
    const float* att_dst_m = (const float*)d_in[24];
    const float* bm        = (const float*)d_in[25];
    const float* Wih_m     = (const float*)d_in[26];
    const float* Whh_m     = (const float*)d_in[27];
    const float* bih_m     = (const float*)d_in[28];
    const float* bhh_m     = (const float*)d_in[29];
    const float* W2        = (const float*)d_in[30];
    const float* b2        = (const float*)d_in[31];

    float *px,*py,*pz,*pt1,*pt2,*pts,*prs,*pcb;
    float *pgout,*pggh,*pgoy,*pgog1,*pgog2,*pgad;
    bf16 *p0hi,*p0lo,*pxhi,*pxlo,*phhi,*phlo,*pwhi,*pwlo;
    cudaGetSymbolAddress((void**)&px,  g_x);
    cudaGetSymbolAddress((void**)&py,  g_y);
    cudaGetSymbolAddress((void**)&pz,  g_z);
    cudaGetSymbolAddress((void**)&pt1, g_t1);
    cudaGetSymbolAddress((void**)&pt2, g_t2);
    cudaGetSymbolAddress((void**)&pts, g_ts);
    cudaGetSymbolAddress((void**)&prs, g_rs);
    cudaGetSymbolAddress((void**)&pcb, g_cb);
    cudaGetSymbolAddress((void**)&pgout, g_gout);
    cudaGetSymbolAddress((void**)&pggh,  g_ggh);
    cudaGetSymbolAddress((void**)&pgoy,  g_goy);
    cudaGetSymbolAddress((void**)&pgog1, g_gog1);
    cudaGetSymbolAddress((void**)&pgog2, g_gog2);
    cudaGetSymbolAddress((void**)&pgad,  g_gad);
    cudaGetSymbolAddress((void**)&p0hi, g_0hi);
    cudaGetSymbolAddress((void**)&p0lo, g_0lo);
    cudaGetSymbolAddress((void**)&pxhi, g_xhi);
    cudaGetSymbolAddress((void**)&pxlo, g_xlo);
    cudaGetSymbolAddress((void**)&phhi, g_hhi);
    cudaGetSymbolAddress((void**)&phlo, g_hlo);
    cudaGetSymbolAddress((void**)&pwhi, g_whi);
    cudaGetSymbolAddress((void**)&pwlo, g_wlo);

    static int smem_set = 0;
    if (!smem_set) {
        cudaFuncSetAttribute(hgemm_mma, cudaFuncAttributeMaxDynamicSharedMemorySize, MM_SMEM);
        cudaFuncSetAttribute(hgemm_dual, cudaFuncAttributeMaxDynamicSharedMemorySize, MM_SMEM);
        smem_set = 1;
    }

    const int RB = (NN + 127) / 128;
    const int EB   = (NE + 255) / 256;
    const int NB4  = (NN*32 + 255) / 256;
    const int DWB  = (NN*32 + 255) / 256;
    const int DGB  = (NG*32 + 255) / 256;
    const int AGG  = (NN*32 + 255) / 256;

    WPtrs wp;
    wp.p[0]=W1; wp.p[1]=Wg1; wp.p[2]=Wg2; wp.p[3]=Wih0; wp.p[4]=Whh0;
    wp.p[5]=Wa; wp.p[6]=Wa+128*128; wp.p[7]=Wih_a; wp.p[8]=Wih_a+384*128;
    wp.p[9]=Whh_a; wp.p[10]=Whh_a+384*128; wp.p[11]=Wm;

    // ---- prologue (idx 3 = K=128 WG2 GEMM: lands in ncu profile slot) ----
    conv_weights<<<dim3(64, 12), 256>>>(wp);
    conv_act<<<(NN*32 + 255)/256, 256>>>(x0, p0hi, p0lo, NN*32);
    hgemm_mma<<<dim3(2, RB), 256, MM_SMEM>>>(p0hi, p0lo, pwhi+OFF_W1, pwlo+OFF_W1,
                                             b1, px, pxhi, pxlo, NN, 64, 128, 1);
    hgemm_mma<<<dim3(2, RB), 256, MM_SMEM>>>(pxhi, pxlo, pwhi+OFF_WG2, pwlo+OFF_WG2,
                                             nullptr, pz, nullptr, nullptr, NN, 128, 128, 0);
    cbias_k<<<1, 128>>>(Wg1);
    csr_zero<<<(NN + 255)/256, 256>>>();
    csr_hist<<<EB, 256>>>(ei);
    csr_scan<<<1, 1024>>>();
    csr_fill<<<EB, 256>>>(ei);

    // ---- GATEConv ----
    hgemm_mma<<<dim3(2, RB), 256, MM_SMEM>>>(pxhi, pxlo, pwhi+OFF_WG1, pwlo+OFF_WG1,
                                             pcb, py, nullptr, nullptr, NN, 128, 128, 1);
    rowdot2<<<DWB, 256>>>(py, att_l, px, att_r, pts, prs, NN);
    gat_agg<<<AGG, 256>>>(pts, prs, pz, bg);
    {
        GSet s0 = { phhi, phlo, pwhi+OFF_WIH0, pwlo+OFF_WIH0, bih0, pt1 };
        GSet s1 = { pxhi, pxlo, pwhi+OFF_WHH0, pwlo+OFF_WHH0, bhh0, pt2 };
        hgemm_dual<<<dim3(12, RB), 256, MM_SMEM>>>(s0, s1, NN);
    }
    gru_elem<<<NB4, 256>>>(pt1, pt2, px, pxhi, pxlo, NN);

    // ---- 2 GATConv layers ----
    for (int l = 0; l < 2; l++) {
        hgemm_mma<<<dim3(2, RB), 256, MM_SMEM>>>(pxhi, pxlo,
                                                 pwhi+OFF_WA+l*16384, pwlo+OFF_WA+l*16384,
                                                 nullptr, pz, nullptr, nullptr, NN, 128, 128, 0);
        rowdot2<<<DWB, 256>>>(pz, att_src_a + l*128, pz, att_dst_a + l*128, pts, prs, NN);
        gat_agg<<<AGG, 256>>>(pts, prs, pz, ba + l*128);
        {
            GSet s0 = { phhi, phlo, pwhi+OFF_WIHA+l*49152, pwlo+OFF_WIHA+l*49152,
                        bih_a + l*384, pt1 };
            GSet s1 = { pxhi, pxlo, pwhi+OFF_WHHA+l*49152, pwlo+OFF_WHHA+l*49152,
                        bhh_a + l*384, pt2 };
            hgemm_dual<<<dim3(12, RB), 256, MM_SMEM>>>(s0, s1, NN);
        }
        gru_elem<<<NB4, 256>>>(pt1, pt2, px, pxhi, pxlo, NN);
    }

    // ---- attentive readout ----
    seg_offsets<<<5, 256>>>(batch);
    readout_sum<<<NG, 128>>>(px);
    hgemm_mma<<<dim3(2, RB), 256, MM_SMEM>>>(pxhi, pxlo, pwhi+OFF_WM, pwlo+OFF_WM,
                                             nullptr, pz, nullptr, nullptr, NN, 128, 128, 0);
    rowdot2<<<DWB, 256>>>(pz, att_src_m, pz, att_src_m, pts, nullptr, NN);

    for (int t = 0; t < 3; t++) {
        sgemm_bias_act<<<dim3(2, 16), 256>>>(pgout, Wm, nullptr, pgoy, NG, 128, 128, 128, 0);
        rowdot2<<<DGB, 256>>>(pgoy, att_dst_m, pgoy, att_dst_m, pgad, nullptr, NG);
        readout_attn<<<NG, 128>>>(pts, pgad, pz, bm);
        sgemm_bias_act<<<dim3(6, 16), 256>>>(pggh,  Wih_m, bih_m, pgog1, NG, 128, 128, 384, 0);
        sgemm_bias_act<<<dim3(6, 16), 256>>>(pgout, Whh_m, bhh_m, pgog2, NG, 128, 128, 384, 0);
        gru_elem<<<(NG*32 + 255)/256, 256>>>(pgog1, pgog2, pgout, nullptr, nullptr, NG);
    }

    final_out<<<NG, 128>>>(W2, b2, (float*)d_out);
}

// round 14
// speedup vs baseline: 1.2665x; 1.0168x over previous
#include <cuda_runtime.h>
#include <cuda_bf16.h>
#include <cstdint>
#include <math.h>

#define NN 50000
#define NE 800000
#define NG 1024

typedef __nv_bfloat16 bf16;
typedef __nv_bfloat162 bf162;

// ---------------- scratch (device globals; no allocation allowed) ----------------
__device__ float g_x [NN*128];
__device__ float g_y [NN*128];
__device__ float g_z [NN*128];
__device__ float g_t1[NN*384];
__device__ float g_t2[NN*384];
__device__ float g_ts[NN];
__device__ float g_rs[NN];
__device__ float g_e [NE];
__device__ int   g_deg[NN];
__device__ int   g_cur[NN];
__device__ int   g_rowptr[NN+1];
__device__ int   g_csr[NE];
__device__ int   g_off[NG+1];
__device__ float g_cb[128];
__device__ float g_gout[NG*128];
__device__ float g_ggh [NG*128];
__device__ float g_goy [NG*128];
__device__ float g_gog1[NG*384];
__device__ float g_gog2[NG*384];
__device__ float g_gad [NG];

// bf16 hi/lo activation buffers
__device__ __align__(16) bf16 g_0hi[NN*64];
__device__ __align__(16) bf16 g_0lo[NN*64];
__device__ __align__(16) bf16 g_xhi[NN*128];
__device__ __align__(16) bf16 g_xlo[NN*128];
__device__ __align__(16) bf16 g_hhi[NN*128];
__device__ __align__(16) bf16 g_hlo[NN*128];

// bf16 hi/lo weight scratch (packed, ld = K)
#define OFF_W1    0
#define OFF_WG1   8192
#define OFF_WG2   24576
#define OFF_WIH0  40960
#define OFF_WHH0  90112
#define OFF_WA    139264
#define OFF_WIHA  172032
#define OFF_WHHA  270336
#define OFF_WM    368640
#define W_TOTAL   385024
__device__ __align__(16) bf16 g_whi[W_TOTAL];
__device__ __align__(16) bf16 g_wlo[W_TOTAL];

// ---------------- helpers ----------------
__device__ __forceinline__ float leakyf(float v){ return v >= 0.f ? v : 0.01f*v; }
__device__ __forceinline__ float sigmf (float v){ return 1.f/(1.f+expf(-v)); }
__device__ __forceinline__ float eluf  (float v){ return v > 0.f ? v : (expf(v)-1.f); }

// =======================================================================
// weight conversion: all 12 node-GEMM weights -> packed bf16 hi/lo
// =======================================================================
struct WPtrs { const float* p[12]; };

__global__ void conv_weights(WPtrs wp)
{
    const int rows[12] = {128,128,128,384,384,128,128,384,384,384,384,128};
    const int cols[12] = { 64,128,128,128,128,128,128,128,128,128,128,128};
    const int ldws[12] = { 64,153,128,128,128,128,128,128,128,128,128,128};
    const int offs[12] = {OFF_W1,OFF_WG1,OFF_WG2,OFF_WIH0,OFF_WHH0,
                          OFF_WA,OFF_WA+16384,OFF_WIHA,OFF_WIHA+49152,
                          OFF_WHHA,OFF_WHHA+49152,OFF_WM};
    int s = blockIdx.y;
    const float* src = wp.p[s];
    int n = rows[s]*cols[s];
    for (int i = blockIdx.x*blockDim.x + threadIdx.x; i < n; i += gridDim.x*blockDim.x) {
        int r = i / cols[s], c = i - r*cols[s];
        float v = src[(size_t)r*ldws[s] + c];
        bf16 h = __float2bfloat16(v);
        g_whi[offs[s] + i] = h;
        g_wlo[offs[s] + i] = __float2bfloat16(v - __bfloat162float(h));
    }
}

__global__ void conv_act(const float* __restrict__ src, bf16* __restrict__ hi,
                         bf16* __restrict__ lo, int n2)
{
    int i = blockIdx.x*blockDim.x + threadIdx.x;
    if (i >= n2) return;
    float2 v = *(const float2*)(src + i*2);
    bf16 hx = __float2bfloat16(v.x), hy = __float2bfloat16(v.y);
    *(bf162*)(hi + i*2) = __halves2bfloat162(hx, hy);
    *(bf162*)(lo + i*2) = __halves2bfloat162(__float2bfloat16(v.x - __bfloat162float(hx)),
                                             __float2bfloat16(v.y - __bfloat162float(hy)));
}

// =======================================================================
// bf16 split-precision tensor-core GEMM body (measured-best R11 structure)
// =======================================================================
#define LDA 72
#define ABUF (128*LDA)
#define WBUF (64*LDA)
#define MM_SMEM ((2*ABUF + 2*WBUF)*2)   // 55296 bytes

__device__ __forceinline__ void mma16816(float* c, const uint32_t* a, const uint32_t* b){
    asm volatile(
        "mma.sync.aligned.m16n8k16.row.col.f32.bf16.bf16.f32 "
        "{%0,%1,%2,%3}, {%4,%5,%6,%7}, {%8,%9}, {%0,%1,%2,%3};\n"
        : "+f"(c[0]), "+f"(c[1]), "+f"(c[2]), "+f"(c[3])
        : "r"(a[0]), "r"(a[1]), "r"(a[2]), "r"(a[3]), "r"(b[0]), "r"(b[1]));
}
__device__ __forceinline__ void ldsm4(uint32_t* r, uint32_t addr){
    asm volatile("ldmatrix.sync.aligned.m8n8.x4.shared.b16 {%0,%1,%2,%3}, [%4];"
        : "=r"(r[0]), "=r"(r[1]), "=r"(r[2]), "=r"(r[3]) : "r"(addr));
}
__device__ __forceinline__ void cpa16(uint32_t dst, const void* src, int sz){
    asm volatile("cp.async.cg.shared.global [%0], [%1], 16, %2;"
        :: "r"(dst), "l"(src), "r"(sz));
}

__device__ __forceinline__ void gemm_body(
    const bf16* __restrict__ Ahi, const bf16* __restrict__ Alo,
    const bf16* __restrict__ Whi, const bf16* __restrict__ Wlo,
    const float* __restrict__ bias, float* __restrict__ C,
    bf16* __restrict__ Chi, bf16* __restrict__ Clo,
    int N, int K, int Ko, int act, int row0, int col0, bf16* sm)
{
    bf16* sAhi = sm;
    bf16* sAlo = sm + ABUF;
    bf16* sBhi = sm + 2*ABUF;
    bf16* sBlo = sm + 2*ABUF + WBUF;

    const int tid  = threadIdx.x;
    const int wid  = tid >> 5, lane = tid & 31;
    const int wm   = wid & 3,  wn   = wid >> 2;
    const int gid  = lane >> 2, tig = lane & 3;

    const int arow = wm*32 + (lane & 15);
    const int acol = (lane >> 4) << 3;
    const int brow = wn*32 + ((lane >> 4) << 3) + (lane & 7);
    const int bcol = ((lane >> 3) & 1) << 3;

    const uint32_t uAhi = (uint32_t)__cvta_generic_to_shared(sAhi);
    const uint32_t uAlo = (uint32_t)__cvta_generic_to_shared(sAlo);
    const uint32_t uBhi = (uint32_t)__cvta_generic_to_shared(sBhi);
    const uint32_t uBlo = (uint32_t)__cvta_generic_to_shared(sBlo);

    float acc[2][4][4];
    #pragma unroll
    for (int mt = 0; mt < 2; mt++)
        #pragma unroll
        for (int nt = 0; nt < 4; nt++)
            #pragma unroll
            for (int q = 0; q < 4; q++) acc[mt][nt][q] = 0.f;

    for (int kc = 0; kc < K; kc += 64) {
        #pragma unroll
        for (int i = tid; i < 1024; i += 256) {
            int r = i >> 3, cc = (i & 7) * 8;
            int gr = row0 + r;
            int grc = gr < N ? gr : 0;
            int sz = gr < N ? 16 : 0;
            uint32_t d = (uint32_t)(r*LDA + cc)*2;
            cpa16(uAhi + d, Ahi + (size_t)grc*K + kc + cc, sz);
            cpa16(uAlo + d, Alo + (size_t)grc*K + kc + cc, sz);
        }
        #pragma unroll
        for (int i = tid; i < 512; i += 256) {
            int r = i >> 3, cc = (i & 7) * 8;
            uint32_t d = (uint32_t)(r*LDA + cc)*2;
            cpa16(uBhi + d, Whi + (size_t)(col0 + r)*K + kc + cc, 16);
            cpa16(uBlo + d, Wlo + (size_t)(col0 + r)*K + kc + cc, 16);
        }
        asm volatile("cp.async.commit_group;");
        asm volatile("cp.async.wait_group 0;");
        __syncthreads();

        const uint32_t At[3] = { uAhi, uAhi, uAlo };
        const uint32_t Bt[3] = { uBhi, uBlo, uBhi };

        #pragma unroll 1
        for (int t = 0; t < 3; t++) {
            uint32_t abase = At[t] + (uint32_t)(arow*LDA + acol)*2;
            uint32_t bbase = Bt[t] + (uint32_t)(brow*LDA + bcol)*2;
            #pragma unroll
            for (int k0 = 0; k0 < 64; k0 += 16) {
                uint32_t af[2][4], bf[2][4];
                ldsm4(af[0], abase + k0*2);
                ldsm4(af[1], abase + (16*LDA + k0)*2);
                ldsm4(bf[0], bbase + k0*2);
                ldsm4(bf[1], bbase + (16*LDA + k0)*2);
                #pragma unroll
                for (int mt = 0; mt < 2; mt++) {
                    mma16816(acc[mt][0], af[mt], bf[0]);
                    mma16816(acc[mt][1], af[mt], bf[0] + 2);
                    mma16816(acc[mt][2], af[mt], bf[1]);
                    mma16816(acc[mt][3], af[mt], bf[1] + 2);
                }
            }
        }
        __syncthreads();
    }

    #pragma unroll
    for (int mt = 0; mt < 2; mt++) {
        int gr0 = row0 + wm*32 + mt*16 + gid;
        #pragma unroll
        for (int half = 0; half < 2; half++) {
            int r = gr0 + half*8;
            if (r >= N) continue;
            #pragma unroll
            for (int nt = 0; nt < 4; nt++) {
                int gc = col0 + wn*32 + nt*8 + tig*2;
                float v0 = acc[mt][nt][half*2+0];
                float v1 = acc[mt][nt][half*2+1];
                if (bias) { v0 += bias[gc]; v1 += bias[gc+1]; }
                if (act == 1) { v0 = leakyf(v0); v1 = leakyf(v1); }
                *(float2*)(C + (size_t)r*Ko + gc) = make_float2(v0, v1);
                if (Chi) {
                    bf16 h0 = __float2bfloat16(v0), h1 = __float2bfloat16(v1);
                    *(bf162*)(Chi + (size_t)r*Ko + gc) = __halves2bfloat162(h0, h1);
                    *(bf162*)(Clo + (size_t)r*Ko + gc) =
                        __halves2bfloat162(__float2bfloat16(v0 - __bfloat162float(h0)),
                                           __float2bfloat16(v1 - __bfloat162float(h1)));
                }
            }
        }
    }
}

__global__ void __launch_bounds__(256, 4)
hgemm_mma(const bf16* __restrict__ Ahi, const bf16* __restrict__ Alo,
          const bf16* __restrict__ Whi, const bf16* __restrict__ Wlo,
          const float* __restrict__ bias, float* __restrict__ C,
          bf16* __restrict__ Chi, bf16* __restrict__ Clo,
          int N, int K, int Ko, int act)
{
    extern __shared__ bf16 sm[];
    gemm_body(Ahi, Alo, Whi, Wlo, bias, C, Chi, Clo, N, K, Ko, act,
              blockIdx.y*128, blockIdx.x*64, sm);
}

// generalized dual launch: blockIdx.x < tiles0 -> set0, else set1. K=128.
struct GSet { const bf16 *Ahi, *Alo, *Whi, *Wlo; const float* bias; float* C; int Ko, act; };

__global__ void __launch_bounds__(256, 4)
hgemm_dual(GSet s0, GSet s1, int tiles0, int N)
{
    extern __shared__ bf16 sm[];
    bool second = blockIdx.x >= tiles0;
    const GSet& s = second ? s1 : s0;
    int col0 = (blockIdx.x - (second ? tiles0 : 0)) * 64;
    gemm_body(s.Ahi, s.Alo, s.Whi, s.Wlo, s.bias, s.C, nullptr, nullptr,
              N, 128, s.Ko, s.act, blockIdx.y*128, col0, sm);
}

// ---------------- small GEMM body (graph-level, fp32, 64x64 tiles) ----------------
__device__ __forceinline__ void sgemm_body(
    const float* __restrict__ A, const float* __restrict__ W,
    const float* __restrict__ bias, float* __restrict__ C,
    int N, int M, int ldw, int Ko, int act, int row0, int col0)
{
    __shared__ float sA[16][64];
    __shared__ float sB[16][64];
    const int tid = threadIdx.x;
    const int tx = tid & 15, ty = tid >> 4;

    float acc[4][4];
    #pragma unroll
    for (int i = 0; i < 4; i++)
        #pragma unroll
        for (int j = 0; j < 4; j++) acc[i][j] = 0.f;

    const int r  = tid >> 2;
    const int kq = (tid & 3) * 4;

    for (int k0 = 0; k0 < M; k0 += 16) {
        int gr = row0 + r;
        float4 av;
        if (gr < N) av = *(const float4*)(A + (size_t)gr*M + k0 + kq);
        else        av = make_float4(0.f,0.f,0.f,0.f);
        sA[kq+0][r]=av.x; sA[kq+1][r]=av.y; sA[kq+2][r]=av.z; sA[kq+3][r]=av.w;

        float4 bv = *(const float4*)(W + (size_t)(col0 + r)*ldw + k0 + kq);
        sB[kq+0][r]=bv.x; sB[kq+1][r]=bv.y; sB[kq+2][r]=bv.z; sB[kq+3][r]=bv.w;
        __syncthreads();

        #pragma unroll
        for (int kk = 0; kk < 16; kk++) {
            float ra[4], rb[4];
            #pragma unroll
            for (int i = 0; i < 4; i++) ra[i] = sA[kk][ty*4+i];
            #pragma unroll
            for (int j = 0; j < 4; j++) rb[j] = sB[kk][tx*4+j];
            #pragma unroll
            for (int i = 0; i < 4; i++)
                #pragma unroll
                for (int j = 0; j < 4; j++) acc[i][j] = fmaf(ra[i], rb[j], acc[i][j]);
        }
        __syncthreads();
    }

    #pragma unroll
    for (int i = 0; i < 4; i++) {
        int gr = row0 + ty*4 + i;
        if (gr >= N) continue;
        #pragma unroll
        for (int j = 0; j < 4; j++) {
            int gc = col0 + tx*4 + j;
            float v = acc[i][j];
            if (bias) v += bias[gc];
            if (act == 1) v = leakyf(v);
            C[(size_t)gr*Ko + gc] = v;
        }
    }
}

__global__ void sgemm_bias_act(const float* __restrict__ A, const float* __restrict__ W,
                               const float* __restrict__ bias, float* __restrict__ C,
                               int N, int M, int ldw, int Ko, int act)
{
    sgemm_body(A, W, bias, C, N, M, ldw, Ko, act, blockIdx.y*64, blockIdx.x*64);
}

struct SSet { const float *A, *W, *bias; float* C; };

__global__ void sgemm_dual(SSet s0, SSet s1, int tiles0, int N)
{
    bool second = blockIdx.x >= tiles0;
    const SSet& s = second ? s1 : s0;
    int col0 = (blockIdx.x - (second ? tiles0 : 0)) * 64;
    sgemm_body(s.A, s.W, s.bias, s.C, N, 128, 128, 384, 0, blockIdx.y*64, col0);
}

// ---------------- per-node dual dot ----------------
__global__ void rowdot2(const float* __restrict__ A, const float* __restrict__ v1,
                        const float* __restrict__ B, const float* __restrict__ v2,
                        float* __restrict__ o1, float* __restrict__ o2, int N)
{
    int gw = (blockIdx.x*blockDim.x + threadIdx.x) >> 5;
    int lane = threadIdx.x & 31;
    if (gw >= N) return;
    const float4 a = *(const float4*)(A + (size_t)gw*128 + lane*4);
    const float4 b = *(const float4*)(B + (size_t)gw*128 + lane*4);
    const float4 u = *(const float4*)(v1 + lane*4);
    const float4 w = *(const float4*)(v2 + lane*4);
    float s1 = a.x*u.x + a.y*u.y + a.z*u.z + a.w*u.w;
    float s2 = b.x*w.x + b.y*w.y + b.z*w.z + b.w*w.w;
    #pragma unroll
    for (int o = 16; o; o >>= 1) {
        s1 += __shfl_xor_sync(0xffffffffu, s1, o);
        s2 += __shfl_xor_sync(0xffffffffu, s2, o);
    }
    if (lane == 0) { o1[gw] = s1; if (o2) o2[gw] = s2; }
}

// ======================= CSR build =======================
__global__ void csr_zero()
{
    int i = blockIdx.x*blockDim.x + threadIdx.x;
    if (i < NN) { g_deg[i] = 0; g_cur[i] = 0; }
}

__global__ void csr_hist(const int* __restrict__ ei)
{
    int e = blockIdx.x*blockDim.x + threadIdx.x;
    if (e >= NE) return;
    atomicAdd(&g_deg[ei[NE+e]], 1);
}

__global__ void __launch_bounds__(1024) csr_scan()
{
    __shared__ int wsum[32];
    const int t = threadIdx.x, lane = t & 31, w = t >> 5;
    const int CH = (NN + 1023) / 1024;
    const int base = t*CH;
    const int end = min(base + CH, NN);
    int sum = 0;
    for (int i = base; i < end; i++) sum += g_deg[i];
    int v = sum;
    #pragma unroll
    for (int o = 1; o < 32; o <<= 1) {
        int u = __shfl_up_sync(0xffffffffu, v, o);
        if (lane >= o) v += u;
    }
    if (lane == 31) wsum[w] = v;
    __syncthreads();
    if (w == 0) {
        int s = wsum[lane];
        #pragma unroll
        for (int o = 1; o < 32; o <<= 1) {
            int u = __shfl_up_sync(0xffffffffu, s, o);
            if (lane >= o) s += u;
        }
        wsum[lane] = s;
    }
    __syncthreads();
    int off = v - sum + (w ? wsum[w-1] : 0);
    for (int i = base; i < end; i++) { g_rowptr[i] = off; off += g_deg[i]; }
    if (t == 1023) g_rowptr[NN] = NE;
}

__global__ void csr_fill(const int* __restrict__ ei)
{
    int e = blockIdx.x*blockDim.x + threadIdx.x;
    if (e >= NE) return;
    int d = ei[NE+e];
    int slot = atomicAdd(&g_cur[d], 1);
    g_csr[g_rowptr[d] + slot] = ei[e];
}

// =======================================================================
// Fused GAT aggregation: warp per dst node; unroll-2 edge loop.
// =======================================================================
__global__ void __launch_bounds__(256)
gat_agg(const float* __restrict__ as, const float* __restrict__ ad,
        const float* __restrict__ msg, const float* __restrict__ bias)
{
    int w = (blockIdx.x*blockDim.x + threadIdx.x) >> 5;
    int lane = threadIdx.x & 31;
    if (w >= NN) return;
    const int s = g_rowptr[w], e = g_rowptr[w+1];
    const float adv = ad[w];

    float mx = -3.402823e38f;
    for (int j = s + lane; j < e; j += 32)
        mx = fmaxf(mx, leakyf(as[g_csr[j]] + adv));
    #pragma unroll
    for (int o = 16; o; o >>= 1)
        mx = fmaxf(mx, __shfl_xor_sync(0xffffffffu, mx, o));

    float ssum = 0.f;
    float4 acc = make_float4(0.f,0.f,0.f,0.f);
    int j = s;
    for (; j + 1 < e; j += 2) {
        int s0 = g_csr[j], s1 = g_csr[j+1];
        float w0 = expf(leakyf(as[s0] + adv) - mx);
        float w1 = expf(leakyf(as[s1] + adv) - mx);
        ssum += w0 + w1;
        float4 m0 = *(const float4*)(msg + (size_t)s0*128 + lane*4);
        float4 m1 = *(const float4*)(msg + (size_t)s1*128 + lane*4);
        acc.x = fmaf(w0, m0.x, fmaf(w1, m1.x, acc.x));
        acc.y = fmaf(w0, m0.y, fmaf(w1, m1.y, acc.y));
        acc.z = fmaf(w0, m0.z, fmaf(w1, m1.z, acc.z));
        acc.w = fmaf(w0, m0.w, fmaf(w1, m1.w, acc.w));
    }
    if (j < e) {
        int s0 = g_csr[j];
        float w0 = expf(leakyf(as[s0] + adv) - mx);
        ssum += w0;
        float4 m0 = *(const float4*)(msg + (size_t)s0*128 + lane*4);
        acc.x = fmaf(w0, m0.x, acc.x);
        acc.y = fmaf(w0, m0.y, acc.y);
        acc.z = fmaf(w0, m0.z, acc.z);
        acc.w = fmaf(w0, m0.w, acc.w);
    }
    float inv = 1.f / (ssum + 1e-16f);
    float4 bv = *(const float4*)(bias + lane*4);
    float o0 = eluf(acc.x*inv + bv.x);
    float o1 = eluf(acc.y*inv + bv.y);
    float o2 = eluf(acc.z*inv + bv.z);
    float o3 = eluf(acc.w*inv + bv.w);

    size_t base = (size_t)w*128 + lane*4;
    bf16 h0 = __float2bfloat16(o0), h1 = __float2bfloat16(o1);
    bf16 h2 = __float2bfloat16(o2), h3 = __float2bfloat16(o3);
    *(bf162*)(g_hhi + base)     = __halves2bfloat162(h0, h1);
    *(bf162*)(g_hhi + base + 2) = __halves2bfloat162(h2, h3);
    *(bf162*)(g_hlo + base)     = __halves2bfloat162(__float2bfloat16(o0 - __bfloat162float(h0)),
                                                     __float2bfloat16(o1 - __bfloat162float(h1)));
    *(bf162*)(g_hlo + base + 2) = __halves2bfloat162(__float2bfloat16(o2 - __bfloat162float(h2)),
                                                     __float2bfloat16(o3 - __bfloat162float(h3)));
}

// ---------------- elementwise GRU: x_new = relu(gru); writes float + bf16 hi/lo ----
__global__ void gru_elem(const float* __restrict__ gi, const float* __restrict__ gh,
                         float* __restrict__ hstate, bf16* __restrict__ ohi,
                         bf16* __restrict__ olo, int rows)
{
    int i = blockIdx.x*blockDim.x + threadIdx.x;
    if (i >= rows*32) return;
    int n = i >> 5, q = (i & 31) * 4;
    const float* a = gi + (size_t)n*384 + q;
    const float* b = gh + (size_t)n*384 + q;
    float4 ai = *(const float4*)(a);
    float4 az = *(const float4*)(a + 128);
    float4 an = *(const float4*)(a + 256);
    float4 bi = *(const float4*)(b);
    float4 bz = *(const float4*)(b + 128);
    float4 bn = *(const float4*)(b + 256);
    float4 hv = *(float4*)(hstate + (size_t)n*128 + q);

    float r, z, nn, v;
    r = sigmf(ai.x + bi.x); z = sigmf(az.x + bz.x); nn = tanhf(an.x + r*bn.x);
    v = (1.f - z)*nn + z*hv.x; hv.x = v > 0.f ? v : 0.f;
    r = sigmf(ai.y + bi.y); z = sigmf(az.y + bz.y); nn = tanhf(an.y + r*bn.y);
    v = (1.f - z)*nn + z*hv.y; hv.y = v > 0.f ? v : 0.f;
    r = sigmf(ai.z + bi.z); z = sigmf(az.z + bz.z); nn = tanhf(an.z + r*bn.z);
    v = (1.f - z)*nn + z*hv.z; hv.z = v > 0.f ? v : 0.f;
    r = sigmf(ai.w + bi.w); z = sigmf(az.w + bz.w); nn = tanhf(an.w + r*bn.w);
    v = (1.f - z)*nn + z*hv.w; hv.w = v > 0.f ? v : 0.f;

    *(float4*)(hstate + (size_t)n*128 + q) = hv;

    if (ohi) {
        size_t base = (size_t)n*128 + q;
        bf16 h0 = __float2bfloat16(hv.x), h1 = __float2bfloat16(hv.y);
        bf16 h2 = __float2bfloat16(hv.z), h3 = __float2bfloat16(hv.w);
        *(bf162*)(ohi + base)     = __halves2bfloat162(h0, h1);
        *(bf162*)(ohi + base + 2) = __halves2bfloat162(h2, h3);
        *(bf162*)(olo + base)     = __halves2bfloat162(__float2bfloat16(hv.x - __bfloat162float(h0)),
                                                       __float2bfloat16(hv.y - __bfloat162float(h1)));
        *(bf162*)(olo + base + 2) = __halves2bfloat162(__float2bfloat16(hv.z - __bfloat162float(h2)),
                                                       __float2bfloat16(hv.w - __bfloat162float(h3)));
    }
}

// ---------------- GATE edge-MLP constant bias ----------------
__global__ void cbias_k(const float* __restrict__ Wg1)
{
    int k = threadIdx.x;
    float c = 0.f;
    for (int j = 128; j < 153; j++) c += Wg1[k*153 + j];
    g_cb[k] = c;
}

// ---------------- readout ----------------
__global__ void seg_offsets(const int* __restrict__ batch)
{
    int g = blockIdx.x*blockDim.x + threadIdx.x;
    if (g > NG) return;
    int lo = 0, hi = NN;
    while (lo < hi) { int mid = (lo+hi) >> 1; if (batch[mid] < g) lo = mid+1; else hi = mid; }
    g_off[g] = lo;
}

__global__ void readout_sum(const float* __restrict__ x)
{
    int g = blockIdx.x, k = threadIdx.x;
    int s = g_off[g], e = g_off[g+1];
    float acc = 0.f;
    for (int n = s; n < e; n++) acc += x[(size_t)n*128 + k];
    g_gout[g*128 + k] = acc > 0.f ? acc : 0.f;
}

__global__ void readout_attn(const float* __restrict__ asrc, const float* __restrict__ adst,
                             const float* __restrict__ xt, const float* __restrict__ bm)
{
    int g = blockIdx.x, tid = threadIdx.x;   // 128 threads
    int s = g_off[g], e = g_off[g+1];
    float ad = adst[g];
    __shared__ float red[4];

    float mx = -3.402823e38f;
    for (int n = s + tid; n < e; n += 128) mx = fmaxf(mx, leakyf(asrc[n] + ad));
    #pragma unroll
    for (int o = 16; o; o >>= 1) mx = fmaxf(mx, __shfl_xor_sync(0xffffffffu, mx, o));
    if ((tid & 31) == 0) red[tid >> 5] = mx;
    __syncthreads();
    mx = fmaxf(fmaxf(red[0], red[1]), fmaxf(red[2], red[3]));
    __syncthreads();

    float sm = 0.f;
    for (int n = s + tid; n < e; n += 128) {
        float ee = expf(leakyf(asrc[n] + ad) - mx);
        g_e[n] = ee;
        sm += ee;
    }
    #pragma unroll
    for (int o = 16; o; o >>= 1) sm += __shfl_xor_sync(0xffffffffu, sm, o);
    if ((tid & 31) == 0) red[tid >> 5] = sm;
    __syncthreads();
    sm = red[0] + red[1] + red[2] + red[3];
    float inv = 1.f / (sm + 1e-16f);

    float acc = 0.f;
    for (int n = s; n < e; n++) acc = fmaf(xt[(size_t)n*128 + tid], g_e[n], acc);
    g_ggh[g*128 + tid] = eluf(acc*inv + bm[tid]);
}

__global__ void final_out(const float* __restrict__ W2, const float* __restrict__ b2,
                          float* __restrict__ out)
{
    int g = blockIdx.x, tid = threadIdx.x;
    __shared__ float red[4];
    float s = g_gout[g*128 + tid] * W2[tid];
    #pragma unroll
    for (int o = 16; o; o >>= 1) s += __shfl_xor_sync(0xffffffffu, s, o);
    if ((tid & 31) == 0) red[tid >> 5] = s;
    __syncthreads();
    if (tid == 0) out[g] = red[0] + red[1] + red[2] + red[3] + b2[0];
}

// ---------------- host orchestration ----------------
extern "C" void kernel_launch(void* const* d_in, const int* in_sizes, int n_in,
                              void* d_out, int out_size)
{
    const float* x0    = (const float*)d_in[0];
    const int*   ei    = (const int*)  d_in[1];
    const int*   batch = (const int*)  d_in[2];
    const float* W1    = (const float*)d_in[3];
    const float* b1    = (const float*)d_in[4];
    const float* Wg1   = (const float*)d_in[5];
    const float* att_l = (const float*)d_in[6];
    const float* att_r = (const float*)d_in[7];
    const float* Wg2   = (const float*)d_in[8];
    const float* bg    = (const float*)d_in[9];
    const float* Wih0  = (const float*)d_in[10];
    const float* Whh0  = (const float*)d_in[11];
    const float* bih0  = (const float*)d_in[12];
    const float* bhh0  = (const float*)d_in[13];
    const float* Wa        = (const float*)d_in[14];
    const float* att_src_a = (const float*)d_in[15];
    const float* att_dst_a = (const float*)d_in[16];
    const float* ba        = (const float*)d_in[17];
    const float* Wih_a     = (const float*)d_in[18];
    const float* Whh_a     = (const float*)d_in[19];
    const float* bih_a     = (const float*)d_in[20];
    const float* bhh_a     = (const float*)d_in[21];
    const float* Wm        = (const float*)d_in[22];
    const float* att_src_m = (const float*)d_in[23];
    const float* att_dst_m = (const float*)d_in[24];
    const float* bm        = (const float*)d_in[25];
    const float* Wih_m     = (const float*)d_in[26];
    const float* Whh_m     = (const float*)d_in[27];
    const float* bih_m     = (const float*)d_in[28];
    const float* bhh_m     = (const float*)d_in[29];
    const float* W2        = (const float*)d_in[30];
    const float* b2        = (const float*)d_in[31];

    float *px,*py,*pz,*pt1,*pt2,*pts,*prs,*pcb;
    float *pgout,*pggh,*pgoy,*pgog1,*pgog2,*pgad;
    bf16 *p0hi,*p0lo,*pxhi,*pxlo,*phhi,*phlo,*pwhi,*pwlo;
    cudaGetSymbolAddress((void**)&px,  g_x);
    cudaGetSymbolAddress((void**)&py,  g_y);
    cudaGetSymbolAddress((void**)&pz,  g_z);
    cudaGetSymbolAddress((void**)&pt1, g_t1);
    cudaGetSymbolAddress((void**)&pt2, g_t2);
    cudaGetSymbolAddress((void**)&pts, g_ts);
    cudaGetSymbolAddress((void**)&prs, g_rs);
    cudaGetSymbolAddress((void**)&pcb, g_cb);
    cudaGetSymbolAddress((void**)&pgout, g_gout);
    cudaGetSymbolAddress((void**)&pggh,  g_ggh);
    cudaGetSymbolAddress((void**)&pgoy,  g_goy);
    cudaGetSymbolAddress((void**)&pgog1, g_gog1);
    cudaGetSymbolAddress((void**)&pgog2, g_gog2);
    cudaGetSymbolAddress((void**)&pgad,  g_gad);
    cudaGetSymbolAddress((void**)&p0hi, g_0hi);
    cudaGetSymbolAddress((void**)&p0lo, g_0lo);
    cudaGetSymbolAddress((void**)&pxhi, g_xhi);
    cudaGetSymbolAddress((void**)&pxlo, g_xlo);
    cudaGetSymbolAddress((void**)&phhi, g_hhi);
    cudaGetSymbolAddress((void**)&phlo, g_hlo);
    cudaGetSymbolAddress((void**)&pwhi, g_whi);
    cudaGetSymbolAddress((void**)&pwlo, g_wlo);

    static int smem_set = 0;
    if (!smem_set) {
        cudaFuncSetAttribute(hgemm_mma, cudaFuncAttributeMaxDynamicSharedMemorySize, MM_SMEM);
        cudaFuncSetAttribute(hgemm_dual, cudaFuncAttributeMaxDynamicSharedMemorySize, MM_SMEM);
        smem_set = 1;
    }

    const int RB = (NN + 127) / 128;
    const int EB   = (NE + 255) / 256;
    const int NB4  = (NN*32 + 255) / 256;
    const int DWB  = (NN*32 + 255) / 256;
    const int DGB  = (NG*32 + 255) / 256;
    const int AGG  = (NN*32 + 255) / 256;

    WPtrs wp;
    wp.p[0]=W1; wp.p[1]=Wg1; wp.p[2]=Wg2; wp.p[3]=Wih0; wp.p[4]=Whh0;
    wp.p[5]=Wa; wp.p[6]=Wa+128*128; wp.p[7]=Wih_a; wp.p[8]=Wih_a+384*128;
    wp.p[9]=Whh_a; wp.p[10]=Whh_a+384*128; wp.p[11]=Wm;

    // ---- prologue ----
    conv_weights<<<dim3(64, 12), 256>>>(wp);
    conv_act<<<(NN*32 + 255)/256, 256>>>(x0, p0hi, p0lo, NN*32);
    cbias_k<<<1, 128>>>(Wg1);
    hgemm_mma<<<dim3(2, RB), 256, MM_SMEM>>>(p0hi, p0lo, pwhi+OFF_W1, pwlo+OFF_W1,
                                             b1, px, pxhi, pxlo, NN, 64, 128, 1);
    // merged WG1 (leaky, cbias -> py) + WG2 (-> pz): same A = pxhi
    {
        GSet s0 = { pxhi, pxlo, pwhi+OFF_WG1, pwlo+OFF_WG1, pcb,     py, 128, 1 };
        GSet s1 = { pxhi, pxlo, pwhi+OFF_WG2, pwlo+OFF_WG2, nullptr, pz, 128, 0 };
        hgemm_dual<<<dim3(4, RB), 256, MM_SMEM>>>(s0, s1, 2, NN);
    }
    csr_zero<<<(NN + 255)/256, 256>>>();
    csr_hist<<<EB, 256>>>(ei);
    csr_scan<<<1, 1024>>>();
    csr_fill<<<EB, 256>>>(ei);

    // ---- GATEConv ----
    rowdot2<<<DWB, 256>>>(py, att_l, px, att_r, pts, prs, NN);
    gat_agg<<<AGG, 256>>>(pts, prs, pz, bg);
    {
        GSet s0 = { phhi, phlo, pwhi+OFF_WIH0, pwlo+OFF_WIH0, bih0, pt1, 384, 0 };
        GSet s1 = { pxhi, pxlo, pwhi+OFF_WHH0, pwlo+OFF_WHH0, bhh0, pt2, 384, 0 };
        hgemm_dual<<<dim3(12, RB), 256, MM_SMEM>>>(s0, s1, 6, NN);
    }
    gru_elem<<<NB4, 256>>>(pt1, pt2, px, pxhi, pxlo, NN);

    // ---- 2 GATConv layers ----
    for (int l = 0; l < 2; l++) {
        hgemm_mma<<<dim3(2, RB), 256, MM_SMEM>>>(pxhi, pxlo,
                                                 pwhi+OFF_WA+l*16384, pwlo+OFF_WA+l*16384,
                                                 nullptr, pz, nullptr, nullptr, NN, 128, 128, 0);
        rowdot2<<<DWB, 256>>>(pz, att_src_a + l*128, pz, att_dst_a + l*128, pts, prs, NN);
        gat_agg<<<AGG, 256>>>(pts, prs, pz, ba + l*128);
        {
            GSet s0 = { phhi, phlo, pwhi+OFF_WIHA+l*49152, pwlo+OFF_WIHA+l*49152,
                        bih_a + l*384, pt1, 384, 0 };
            GSet s1 = { pxhi, pxlo, pwhi+OFF_WHHA+l*49152, pwlo+OFF_WHHA+l*49152,
                        bhh_a + l*384, pt2, 384, 0 };
            hgemm_dual<<<dim3(12, RB), 256, MM_SMEM>>>(s0, s1, 6, NN);
        }
        gru_elem<<<NB4, 256>>>(pt1, pt2, px, pxhi, pxlo, NN);
    }

    // ---- attentive readout ----
    seg_offsets<<<5, 256>>>(batch);
    readout_sum<<<NG, 128>>>(px);
    hgemm_mma<<<dim3(2, RB), 256, MM_SMEM>>>(pxhi, pxlo, pwhi+OFF_WM, pwlo+OFF_WM,
                                             nullptr, pz, nullptr, nullptr, NN, 128, 128, 0);
    rowdot2<<<DWB, 256>>>(pz, att_src_m, pz, att_src_m, pts, nullptr, NN);

    for (int t = 0; t < 3; t++) {
        sgemm_bias_act<<<dim3(2, 16), 256>>>(pgout, Wm, nullptr, pgoy, NG, 128, 128, 128, 0);
        rowdot2<<<DGB, 256>>>(pgoy, att_dst_m, pgoy, att_dst_m, pgad, nullptr, NG);
        readout_attn<<<NG, 128>>>(pts, pgad, pz, bm);
        {
            SSet s0 = { pggh,  Wih_m, bih_m, pgog1 };
            SSet s1 = { pgout, Whh_m, bhh_m, pgog2 };
            sgemm_dual<<<dim3(12, 16), 256>>>(s0, s1, 6, NG);
        }
        gru_elem<<<(NG*32 + 255)/256, 256>>>(pgog1, pgog2, pgout, nullptr, nullptr, NG);
    }

    final_out<<<NG, 128>>>(W2, b2, (float*)d_out);
}

// round 15
// speedup vs baseline: 1.3059x; 1.0311x over previous
#include <cuda_runtime.h>
#include <cuda_bf16.h>
#include <cstdint>
#include <math.h>

#define NN 50000
#define NE 800000
#define NG 1024

typedef __nv_bfloat16 bf16;
typedef __nv_bfloat162 bf162;

// ---------------- scratch (device globals; no allocation allowed) ----------------
__device__ float g_x [NN*128];
__device__ float g_y [NN*128];
__device__ float g_z [NN*128];
__device__ float g_t1[NN*384];
__device__ float g_t2[NN*384];
__device__ float g_ts[NN];
__device__ float g_rs[NN];
__device__ float g_e [NE];
__device__ int   g_deg[NN];
__device__ int   g_cur[NN];
__device__ int   g_rowptr[NN+1];
__device__ int   g_csr[NE];
__device__ int   g_off[NG+1];
__device__ float g_cb[128];
__device__ float g_vd[128];
__device__ float g_gout[NG*128];
__device__ float g_ggh [NG*128];
__device__ float g_gog1[NG*384];
__device__ float g_gog2[NG*384];

// bf16 hi/lo activation buffers
__device__ __align__(16) bf16 g_0hi[NN*64];
__device__ __align__(16) bf16 g_0lo[NN*64];
__device__ __align__(16) bf16 g_xhi[NN*128];
__device__ __align__(16) bf16 g_xlo[NN*128];
__device__ __align__(16) bf16 g_hhi[NN*128];
__device__ __align__(16) bf16 g_hlo[NN*128];

// bf16 hi/lo weight scratch (packed, ld = K)
#define OFF_W1    0
#define OFF_WG1   8192
#define OFF_WG2   24576
#define OFF_WIH0  40960
#define OFF_WHH0  90112
#define OFF_WA    139264
#define OFF_WIHA  172032
#define OFF_WHHA  270336
#define OFF_WM    368640
#define W_TOTAL   385024
__device__ __align__(16) bf16 g_whi[W_TOTAL];
__device__ __align__(16) bf16 g_wlo[W_TOTAL];

// ---------------- helpers ----------------
__device__ __forceinline__ float leakyf(float v){ return v >= 0.f ? v : 0.01f*v; }
__device__ __forceinline__ float sigmf (float v){ return 1.f/(1.f+expf(-v)); }
__device__ __forceinline__ float eluf  (float v){ return v > 0.f ? v : (expf(v)-1.f); }

// =======================================================================
// weight conversion: all 12 node-GEMM weights -> packed bf16 hi/lo
// =======================================================================
struct WPtrs { const float* p[12]; };

__global__ void conv_weights(WPtrs wp)
{
    const int rows[12] = {128,128,128,384,384,128,128,384,384,384,384,128};
    const int cols[12] = { 64,128,128,128,128,128,128,128,128,128,128,128};
    const int ldws[12] = { 64,153,128,128,128,128,128,128,128,128,128,128};
    const int offs[12] = {OFF_W1,OFF_WG1,OFF_WG2,OFF_WIH0,OFF_WHH0,
                          OFF_WA,OFF_WA+16384,OFF_WIHA,OFF_WIHA+49152,
                          OFF_WHHA,OFF_WHHA+49152,OFF_WM};
    int s = blockIdx.y;
    const float* src = wp.p[s];
    int n = rows[s]*cols[s];
    for (int i = blockIdx.x*blockDim.x + threadIdx.x; i < n; i += gridDim.x*blockDim.x) {
        int r = i / cols[s], c = i - r*cols[s];
        float v = src[(size_t)r*ldws[s] + c];
        bf16 h = __float2bfloat16(v);
        g_whi[offs[s] + i] = h;
        g_wlo[offs[s] + i] = __float2bfloat16(v - __bfloat162float(h));
    }
}

__global__ void conv_act(const float* __restrict__ src, bf16* __restrict__ hi,
                         bf16* __restrict__ lo, int n2)
{
    int i = blockIdx.x*blockDim.x + threadIdx.x;
    if (i >= n2) return;
    float2 v = *(const float2*)(src + i*2);
    bf16 hx = __float2bfloat16(v.x), hy = __float2bfloat16(v.y);
    *(bf162*)(hi + i*2) = __halves2bfloat162(hx, hy);
    *(bf162*)(lo + i*2) = __halves2bfloat162(__float2bfloat16(v.x - __bfloat162float(hx)),
                                             __float2bfloat16(v.y - __bfloat162float(hy)));
}

// GATE edge-MLP constant bias + readout dst-attention vector: ṽ = Wm^T att_dst
__global__ void prep_vecs(const float* __restrict__ Wg1, const float* __restrict__ Wm,
                          const float* __restrict__ att_dst)
{
    int k = threadIdx.x;
    float c = 0.f;
    for (int j = 128; j < 153; j++) c += Wg1[k*153 + j];
    g_cb[k] = c;
    float v = 0.f;
    for (int r = 0; r < 128; r++) v = fmaf(Wm[r*128 + k], att_dst[r], v);
    g_vd[k] = v;
}

// =======================================================================
// bf16 split-precision tensor-core GEMM body (measured-best R11 structure)
// =======================================================================
#define LDA 72
#define ABUF (128*LDA)
#define WBUF (64*LDA)
#define MM_SMEM ((2*ABUF + 2*WBUF)*2)   // 55296 bytes

__device__ __forceinline__ void mma16816(float* c, const uint32_t* a, const uint32_t* b){
    asm volatile(
        "mma.sync.aligned.m16n8k16.row.col.f32.bf16.bf16.f32 "
        "{%0,%1,%2,%3}, {%4,%5,%6,%7}, {%8,%9}, {%0,%1,%2,%3};\n"
        : "+f"(c[0]), "+f"(c[1]), "+f"(c[2]), "+f"(c[3])
        : "r"(a[0]), "r"(a[1]), "r"(a[2]), "r"(a[3]), "r"(b[0]), "r"(b[1]));
}
__device__ __forceinline__ void ldsm4(uint32_t* r, uint32_t addr){
    asm volatile("ldmatrix.sync.aligned.m8n8.x4.shared.b16 {%0,%1,%2,%3}, [%4];"
        : "=r"(r[0]), "=r"(r[1]), "=r"(r[2]), "=r"(r[3]) : "r"(addr));
}
__device__ __forceinline__ void cpa16(uint32_t dst, const void* src, int sz){
    asm volatile("cp.async.cg.shared.global [%0], [%1], 16, %2;"
        :: "r"(dst), "l"(src), "r"(sz));
}

__device__ __forceinline__ void gemm_body(
    const bf16* __restrict__ Ahi, const bf16* __restrict__ Alo,
    const bf16* __restrict__ Whi, const bf16* __restrict__ Wlo,
    const float* __restrict__ bias, float* __restrict__ C,
    bf16* __restrict__ Chi, bf16* __restrict__ Clo,
    int N, int K, int Ko, int act, int row0, int col0, bf16* sm)
{
    bf16* sAhi = sm;
    bf16* sAlo = sm + ABUF;
    bf16* sBhi = sm + 2*ABUF;
    bf16* sBlo = sm + 2*ABUF + WBUF;

    const int tid  = threadIdx.x;
    const int wid  = tid >> 5, lane = tid & 31;
    const int wm   = wid & 3,  wn   = wid >> 2;
    const int gid  = lane >> 2, tig = lane & 3;

    const int arow = wm*32 + (lane & 15);
    const int acol = (lane >> 4) << 3;
    const int brow = wn*32 + ((lane >> 4) << 3) + (lane & 7);
    const int bcol = ((lane >> 3) & 1) << 3;

    const uint32_t uAhi = (uint32_t)__cvta_generic_to_shared(sAhi);
    const uint32_t uAlo = (uint32_t)__cvta_generic_to_shared(sAlo);
    const uint32_t uBhi = (uint32_t)__cvta_generic_to_shared(sBhi);
    const uint32_t uBlo = (uint32_t)__cvta_generic_to_shared(sBlo);

    float acc[2][4][4];
    #pragma unroll
    for (int mt = 0; mt < 2; mt++)
        #pragma unroll
        for (int nt = 0; nt < 4; nt++)
            #pragma unroll
            for (int q = 0; q < 4; q++) acc[mt][nt][q] = 0.f;

    for (int kc = 0; kc < K; kc += 64) {
        #pragma unroll
        for (int i = tid; i < 1024; i += 256) {
            int r = i >> 3, cc = (i & 7) * 8;
            int gr = row0 + r;
            int grc = gr < N ? gr : 0;
            int sz = gr < N ? 16 : 0;
            uint32_t d = (uint32_t)(r*LDA + cc)*2;
            cpa16(uAhi + d, Ahi + (size_t)grc*K + kc + cc, sz);
            cpa16(uAlo + d, Alo + (size_t)grc*K + kc + cc, sz);
        }
        #pragma unroll
        for (int i = tid; i < 512; i += 256) {
            int r = i >> 3, cc = (i & 7) * 8;
            uint32_t d = (uint32_t)(r*LDA + cc)*2;
            cpa16(uBhi + d, Whi + (size_t)(col0 + r)*K + kc + cc, 16);
            cpa16(uBlo + d, Wlo + (size_t)(col0 + r)*K + kc + cc, 16);
        }
        asm volatile("cp.async.commit_group;");
        asm volatile("cp.async.wait_group 0;");
        __syncthreads();

        const uint32_t At[3] = { uAhi, uAhi, uAlo };
        const uint32_t Bt[3] = { uBhi, uBlo, uBhi };

        #pragma unroll 1
        for (int t = 0; t < 3; t++) {
            uint32_t abase = At[t] + (uint32_t)(arow*LDA + acol)*2;
            uint32_t bbase = Bt[t] + (uint32_t)(brow*LDA + bcol)*2;
            #pragma unroll
            for (int k0 = 0; k0 < 64; k0 += 16) {
                uint32_t af[2][4], bf[2][4];
                ldsm4(af[0], abase + k0*2);
                ldsm4(af[1], abase + (16*LDA + k0)*2);
                ldsm4(bf[0], bbase + k0*2);
                ldsm4(bf[1], bbase + (16*LDA + k0)*2);
                #pragma unroll
                for (int mt = 0; mt < 2; mt++) {
                    mma16816(acc[mt][0], af[mt], bf[0]);
                    mma16816(acc[mt][1], af[mt], bf[0] + 2);
                    mma16816(acc[mt][2], af[mt], bf[1]);
                    mma16816(acc[mt][3], af[mt], bf[1] + 2);
                }
            }
        }
        __syncthreads();
    }

    #pragma unroll
    for (int mt = 0; mt < 2; mt++) {
        int gr0 = row0 + wm*32 + mt*16 + gid;
        #pragma unroll
        for (int half = 0; half < 2; half++) {
            int r = gr0 + half*8;
            if (r >= N) continue;
            #pragma unroll
            for (int nt = 0; nt < 4; nt++) {
                int gc = col0 + wn*32 + nt*8 + tig*2;
                float v0 = acc[mt][nt][half*2+0];
                float v1 = acc[mt][nt][half*2+1];
                if (bias) { v0 += bias[gc]; v1 += bias[gc+1]; }
                if (act == 1) { v0 = leakyf(v0); v1 = leakyf(v1); }
                *(float2*)(C + (size_t)r*Ko + gc) = make_float2(v0, v1);
                if (Chi) {
                    bf16 h0 = __float2bfloat16(v0), h1 = __float2bfloat16(v1);
                    *(bf162*)(Chi + (size_t)r*Ko + gc) = __halves2bfloat162(h0, h1);
                    *(bf162*)(Clo + (size_t)r*Ko + gc) =
                        __halves2bfloat162(__float2bfloat16(v0 - __bfloat162float(h0)),
                                           __float2bfloat16(v1 - __bfloat162float(h1)));
                }
            }
        }
    }
}

__global__ void __launch_bounds__(256, 4)
hgemm_mma(const bf16* __restrict__ Ahi, const bf16* __restrict__ Alo,
          const bf16* __restrict__ Whi, const bf16* __restrict__ Wlo,
          const float* __restrict__ bias, float* __restrict__ C,
          bf16* __restrict__ Chi, bf16* __restrict__ Clo,
          int N, int K, int Ko, int act)
{
    extern __shared__ bf16 sm[];
    gemm_body(Ahi, Alo, Whi, Wlo, bias, C, Chi, Clo, N, K, Ko, act,
              blockIdx.y*128, blockIdx.x*64, sm);
}

// generalized dual launch: blockIdx.x < tiles0 -> set0, else set1. K=128.
struct GSet { const bf16 *Ahi, *Alo, *Whi, *Wlo; const float* bias; float* C; int Ko, act; };

__global__ void __launch_bounds__(256, 4)
hgemm_dual(GSet s0, GSet s1, int tiles0, int N)
{
    extern __shared__ bf16 sm[];
    bool second = blockIdx.x >= tiles0;
    const GSet& s = second ? s1 : s0;
    int col0 = (blockIdx.x - (second ? tiles0 : 0)) * 64;
    gemm_body(s.Ahi, s.Alo, s.Whi, s.Wlo, s.bias, s.C, nullptr, nullptr,
              N, 128, s.Ko, s.act, blockIdx.y*128, col0, sm);
}

// ---------------- small GEMM body (graph-level, fp32, 64x64 tiles) ----------------
__device__ __forceinline__ void sgemm_body(
    const float* __restrict__ A, const float* __restrict__ W,
    const float* __restrict__ bias, float* __restrict__ C,
    int N, int M, int ldw, int Ko, int act, int row0, int col0)
{
    __shared__ float sA[16][64];
    __shared__ float sB[16][64];
    const int tid = threadIdx.x;
    const int tx = tid & 15, ty = tid >> 4;

    float acc[4][4];
    #pragma unroll
    for (int i = 0; i < 4; i++)
        #pragma unroll
        for (int j = 0; j < 4; j++) acc[i][j] = 0.f;

    const int r  = tid >> 2;
    const int kq = (tid & 3) * 4;

    for (int k0 = 0; k0 < M; k0 += 16) {
        int gr = row0 + r;
        float4 av;
        if (gr < N) av = *(const float4*)(A + (size_t)gr*M + k0 + kq);
        else        av = make_float4(0.f,0.f,0.f,0.f);
        sA[kq+0][r]=av.x; sA[kq+1][r]=av.y; sA[kq+2][r]=av.z; sA[kq+3][r]=av.w;

        float4 bv = *(const float4*)(W + (size_t)(col0 + r)*ldw + k0 + kq);
        sB[kq+0][r]=bv.x; sB[kq+1][r]=bv.y; sB[kq+2][r]=bv.z; sB[kq+3][r]=bv.w;
        __syncthreads();

        #pragma unroll
        for (int kk = 0; kk < 16; kk++) {
            float ra[4], rb[4];
            #pragma unroll
            for (int i = 0; i < 4; i++) ra[i] = sA[kk][ty*4+i];
            #pragma unroll
            for (int j = 0; j < 4; j++) rb[j] = sB[kk][tx*4+j];
            #pragma unroll
            for (int i = 0; i < 4; i++)
                #pragma unroll
                for (int j = 0; j < 4; j++) acc[i][j] = fmaf(ra[i], rb[j], acc[i][j]);
        }
        __syncthreads();
    }

    #pragma unroll
    for (int i = 0; i < 4; i++) {
        int gr = row0 + ty*4 + i;
        if (gr >= N) continue;
        #pragma unroll
        for (int j = 0; j < 4; j++) {
            int gc = col0 + tx*4 + j;
            float v = acc[i][j];
            if (bias) v += bias[gc];
            if (act == 1) v = leakyf(v);
            C[(size_t)gr*Ko + gc] = v;
        }
    }
}

struct SSet { const float *A, *W, *bias; float* C; };

__global__ void sgemm_dual(SSet s0, SSet s1, int tiles0, int N)
{
    bool second = blockIdx.x >= tiles0;
    const SSet& s = second ? s1 : s0;
    int col0 = (blockIdx.x - (second ? tiles0 : 0)) * 64;
    sgemm_body(s.A, s.W, s.bias, s.C, N, 128, 128, 384, 0, blockIdx.y*64, col0);
}

// ---------------- per-node dual dot ----------------
__global__ void rowdot2(const float* __restrict__ A, const float* __restrict__ v1,
                        const float* __restrict__ B, const float* __restrict__ v2,
                        float* __restrict__ o1, float* __restrict__ o2, int N)
{
    int gw = (blockIdx.x*blockDim.x + threadIdx.x) >> 5;
    int lane = threadIdx.x & 31;
    if (gw >= N) return;
    const float4 a = *(const float4*)(A + (size_t)gw*128 + lane*4);
    const float4 b = *(const float4*)(B + (size_t)gw*128 + lane*4);
    const float4 u = *(const float4*)(v1 + lane*4);
    const float4 w = *(const float4*)(v2 + lane*4);
    float s1 = a.x*u.x + a.y*u.y + a.z*u.z + a.w*u.w;
    float s2 = b.x*w.x + b.y*w.y + b.z*w.z + b.w*w.w;
    #pragma unroll
    for (int o = 16; o; o >>= 1) {
        s1 += __shfl_xor_sync(0xffffffffu, s1, o);
        s2 += __shfl_xor_sync(0xffffffffu, s2, o);
    }
    if (lane == 0) { o1[gw] = s1; if (o2) o2[gw] = s2; }
}

// ======================= CSR build =======================
__global__ void csr_zero()
{
    int i = blockIdx.x*blockDim.x + threadIdx.x;
    if (i < NN) { g_deg[i] = 0; g_cur[i] = 0; }
}

__global__ void csr_hist(const int* __restrict__ ei)
{
    int e = blockIdx.x*blockDim.x + threadIdx.x;
    if (e >= NE) return;
    atomicAdd(&g_deg[ei[NE+e]], 1);
}

__global__ void __launch_bounds__(1024) csr_scan()
{
    __shared__ int wsum[32];
    const int t = threadIdx.x, lane = t & 31, w = t >> 5;
    const int CH = (NN + 1023) / 1024;
    const int base = t*CH;
    const int end = min(base + CH, NN);
    int sum = 0;
    for (int i = base; i < end; i++) sum += g_deg[i];
    int v = sum;
    #pragma unroll
    for (int o = 1; o < 32; o <<= 1) {
        int u = __shfl_up_sync(0xffffffffu, v, o);
        if (lane >= o) v += u;
    }
    if (lane == 31) wsum[w] = v;
    __syncthreads();
    if (w == 0) {
        int s = wsum[lane];
        #pragma unroll
        for (int o = 1; o < 32; o <<= 1) {
            int u = __shfl_up_sync(0xffffffffu, s, o);
            if (lane >= o) s += u;
        }
        wsum[lane] = s;
    }
    __syncthreads();
    int off = v - sum + (w ? wsum[w-1] : 0);
    for (int i = base; i < end; i++) { g_rowptr[i] = off; off += g_deg[i]; }
    if (t == 1023) g_rowptr[NN] = NE;
}

__global__ void csr_fill(const int* __restrict__ ei)
{
    int e = blockIdx.x*blockDim.x + threadIdx.x;
    if (e >= NE) return;
    int d = ei[NE+e];
    int slot = atomicAdd(&g_cur[d], 1);
    g_csr[g_rowptr[d] + slot] = ei[e];
}

// =======================================================================
// Fused GAT aggregation: warp per dst node; unroll-2 edge loop.
// =======================================================================
__global__ void __launch_bounds__(256)
gat_agg(const float* __restrict__ as, const float* __restrict__ ad,
        const float* __restrict__ msg, const float* __restrict__ bias)
{
    int w = (blockIdx.x*blockDim.x + threadIdx.x) >> 5;
    int lane = threadIdx.x & 31;
    if (w >= NN) return;
    const int s = g_rowptr[w], e = g_rowptr[w+1];
    const float adv = ad[w];

    float mx = -3.402823e38f;
    for (int j = s + lane; j < e; j += 32)
        mx = fmaxf(mx, leakyf(as[g_csr[j]] + adv));
    #pragma unroll
    for (int o = 16; o; o >>= 1)
        mx = fmaxf(mx, __shfl_xor_sync(0xffffffffu, mx, o));

    float ssum = 0.f;
    float4 acc = make_float4(0.f,0.f,0.f,0.f);
    int j = s;
    for (; j + 1 < e; j += 2) {
        int s0 = g_csr[j], s1 = g_csr[j+1];
        float w0 = expf(leakyf(as[s0] + adv) - mx);
        float w1 = expf(leakyf(as[s1] + adv) - mx);
        ssum += w0 + w1;
        float4 m0 = *(const float4*)(msg + (size_t)s0*128 + lane*4);
        float4 m1 = *(const float4*)(msg + (size_t)s1*128 + lane*4);
        acc.x = fmaf(w0, m0.x, fmaf(w1, m1.x, acc.x));
        acc.y = fmaf(w0, m0.y, fmaf(w1, m1.y, acc.y));
        acc.z = fmaf(w0, m0.z, fmaf(w1, m1.z, acc.z));
        acc.w = fmaf(w0, m0.w, fmaf(w1, m1.w, acc.w));
    }
    if (j < e) {
        int s0 = g_csr[j];
        float w0 = expf(leakyf(as[s0] + adv) - mx);
        ssum += w0;
        float4 m0 = *(const float4*)(msg + (size_t)s0*128 + lane*4);
        acc.x = fmaf(w0, m0.x, acc.x);
        acc.y = fmaf(w0, m0.y, acc.y);
        acc.z = fmaf(w0, m0.z, acc.z);
        acc.w = fmaf(w0, m0.w, acc.w);
    }
    float inv = 1.f / (ssum + 1e-16f);
    float4 bv = *(const float4*)(bias + lane*4);
    float o0 = eluf(acc.x*inv + bv.x);
    float o1 = eluf(acc.y*inv + bv.y);
    float o2 = eluf(acc.z*inv + bv.z);
    float o3 = eluf(acc.w*inv + bv.w);

    size_t base = (size_t)w*128 + lane*4;
    bf16 h0 = __float2bfloat16(o0), h1 = __float2bfloat16(o1);
    bf16 h2 = __float2bfloat16(o2), h3 = __float2bfloat16(o3);
    *(bf162*)(g_hhi + base)     = __halves2bfloat162(h0, h1);
    *(bf162*)(g_hhi + base + 2) = __halves2bfloat162(h2, h3);
    *(bf162*)(g_hlo + base)     = __halves2bfloat162(__float2bfloat16(o0 - __bfloat162float(h0)),
                                                     __float2bfloat16(o1 - __bfloat162float(h1)));
    *(bf162*)(g_hlo + base + 2) = __halves2bfloat162(__float2bfloat16(o2 - __bfloat162float(h2)),
                                                     __float2bfloat16(o3 - __bfloat162float(h3)));
}

// ---------------- elementwise GRU: x_new = relu(gru); writes float + bf16 hi/lo ----
__global__ void gru_elem(const float* __restrict__ gi, const float* __restrict__ gh,
                         float* __restrict__ hstate, bf16* __restrict__ ohi,
                         bf16* __restrict__ olo, int rows)
{
    int i = blockIdx.x*blockDim.x + threadIdx.x;
    if (i >= rows*32) return;
    int n = i >> 5, q = (i & 31) * 4;
    const float* a = gi + (size_t)n*384 + q;
    const float* b = gh + (size_t)n*384 + q;
    float4 ai = *(const float4*)(a);
    float4 az = *(const float4*)(a + 128);
    float4 an = *(const float4*)(a + 256);
    float4 bi = *(const float4*)(b);
    float4 bz = *(const float4*)(b + 128);
    float4 bn = *(const float4*)(b + 256);
    float4 hv = *(float4*)(hstate + (size_t)n*128 + q);

    float r, z, nn, v;
    r = sigmf(ai.x + bi.x); z = sigmf(az.x + bz.x); nn = tanhf(an.x + r*bn.x);
    v = (1.f - z)*nn + z*hv.x; hv.x = v > 0.f ? v : 0.f;
    r = sigmf(ai.y + bi.y); z = sigmf(az.y + bz.y); nn = tanhf(an.y + r*bn.y);
    v = (1.f - z)*nn + z*hv.y; hv.y = v > 0.f ? v : 0.f;
    r = sigmf(ai.z + bi.z); z = sigmf(az.z + bz.z); nn = tanhf(an.z + r*bn.z);
    v = (1.f - z)*nn + z*hv.z; hv.z = v > 0.f ? v : 0.f;
    r = sigmf(ai.w + bi.w); z = sigmf(az.w + bz.w); nn = tanhf(an.w + r*bn.w);
    v = (1.f - z)*nn + z*hv.w; hv.w = v > 0.f ? v : 0.f;

    *(float4*)(hstate + (size_t)n*128 + q) = hv;

    if (ohi) {
        size_t base = (size_t)n*128 + q;
        bf16 h0 = __float2bfloat16(hv.x), h1 = __float2bfloat16(hv.y);
        bf16 h2 = __float2bfloat16(hv.z), h3 = __float2bfloat16(hv.w);
        *(bf162*)(ohi + base)     = __halves2bfloat162(h0, h1);
        *(bf162*)(ohi + base + 2) = __halves2bfloat162(h2, h3);
        *(bf162*)(olo + base)     = __halves2bfloat162(__float2bfloat16(hv.x - __bfloat162float(h0)),
                                                       __float2bfloat16(hv.y - __bfloat162float(h1)));
        *(bf162*)(olo + base + 2) = __halves2bfloat162(__float2bfloat16(hv.z - __bfloat162float(h2)),
                                                       __float2bfloat16(hv.w - __bfloat162float(h3)));
    }
}

// ---------------- readout ----------------
__global__ void seg_offsets(const int* __restrict__ batch)
{
    int g = blockIdx.x*blockDim.x + threadIdx.x;
    if (g > NG) return;
    int lo = 0, hi = NN;
    while (lo < hi) { int mid = (lo+hi) >> 1; if (batch[mid] < g) lo = mid+1; else hi = mid; }
    g_off[g] = lo;
}

__global__ void readout_sum(const float* __restrict__ x)
{
    int g = blockIdx.x, k = threadIdx.x;
    int s = g_off[g], e = g_off[g+1];
    float acc = 0.f;
    for (int n = s; n < e; n++) acc += x[(size_t)n*128 + k];
    g_gout[g*128 + k] = acc > 0.f ? acc : 0.f;
}

// fused: adst = gout[g]·ṽ (block reduce), then per-graph softmax + aggregate + elu
__global__ void readout_attn(const float* __restrict__ asrc, const float* __restrict__ xt,
                             const float* __restrict__ bm)
{
    int g = blockIdx.x, tid = threadIdx.x;   // 128 threads
    int s = g_off[g], e = g_off[g+1];
    __shared__ float red[4];

    // adst = dot(gout[g], vd)
    float dv = g_gout[g*128 + tid] * g_vd[tid];
    #pragma unroll
    for (int o = 16; o; o >>= 1) dv += __shfl_xor_sync(0xffffffffu, dv, o);
    if ((tid & 31) == 0) red[tid >> 5] = dv;
    __syncthreads();
    float ad = red[0] + red[1] + red[2] + red[3];
    __syncthreads();

    float mx = -3.402823e38f;
    for (int n = s + tid; n < e; n += 128) mx = fmaxf(mx, leakyf(asrc[n] + ad));
    #pragma unroll
    for (int o = 16; o; o >>= 1) mx = fmaxf(mx, __shfl_xor_sync(0xffffffffu, mx, o));
    if ((tid & 31) == 0) red[tid >> 5] = mx;
    __syncthreads();
    mx = fmaxf(fmaxf(red[0], red[1]), fmaxf(red[2], red[3]));
    __syncthreads();

    float sm = 0.f;
    for (int n = s + tid; n < e; n += 128) {
        float ee = expf(leakyf(asrc[n] + ad) - mx);
        g_e[n] = ee;
        sm += ee;
    }
    #pragma unroll
    for (int o = 16; o; o >>= 1) sm += __shfl_xor_sync(0xffffffffu, sm, o);
    if ((tid & 31) == 0) red[tid >> 5] = sm;
    __syncthreads();
    sm = red[0] + red[1] + red[2] + red[3];
    float inv = 1.f / (sm + 1e-16f);

    float acc = 0.f;
    for (int n = s; n < e; n++) acc = fmaf(xt[(size_t)n*128 + tid], g_e[n], acc);
    g_ggh[g*128 + tid] = eluf(acc*inv + bm[tid]);
}

__global__ void final_out(const float* __restrict__ W2, const float* __restrict__ b2,
                          float* __restrict__ out)
{
    int g = blockIdx.x, tid = threadIdx.x;
    __shared__ float red[4];
    float s = g_gout[g*128 + tid] * W2[tid];
    #pragma unroll
    for (int o = 16; o; o >>= 1) s += __shfl_xor_sync(0xffffffffu, s, o);
    if ((tid & 31) == 0) red[tid >> 5] = s;
    __syncthreads();
    if (tid == 0) out[g] = red[0] + red[1] + red[2] + red[3] + b2[0];
}

// ---------------- host orchestration ----------------
extern "C" void kernel_launch(void* const* d_in, const int* in_sizes, int n_in,
                              void* d_out, int out_size)
{
    const float* x0    = (const float*)d_in[0];
    const int*   ei    = (const int*)  d_in[1];
    const int*   batch = (const int*)  d_in[2];
    const float* W1    = (const float*)d_in[3];
    const float* b1    = (const float*)d_in[4];
    const float* Wg1   = (const float*)d_in[5];
    const float* att_l = (const float*)d_in[6];
    const float* att_r = (const float*)d_in[7];
    const float* Wg2   = (const float*)d_in[8];
    const float* bg    = (const float*)d_in[9];
    const float* Wih0  = (const float*)d_in[10];
    const float* Whh0  = (const float*)d_in[11];
    const float* bih0  = (const float*)d_in[12];
    const float* bhh0  = (const float*)d_in[13];
    const float* Wa        = (const float*)d_in[14];
    const float* att_src_a = (const float*)d_in[15];
    const float* att_dst_a = (const float*)d_in[16];
    const float* ba        = (const float*)d_in[17];
    const float* Wih_a     = (const float*)d_in[18];
    const float* Whh_a     = (const float*)d_in[19];
    const float* bih_a     = (const float*)d_in[20];
    const float* bhh_a     = (const float*)d_in[21];
    const float* Wm        = (const float*)d_in[22];
    const float* att_src_m = (const float*)d_in[23];
    const float* att_dst_m = (const float*)d_in[24];
    const float* bm        = (const float*)d_in[25];
    const float* Wih_m     = (const float*)d_in[26];
    const float* Whh_m     = (const float*)d_in[27];
    const float* bih_m     = (const float*)d_in[28];
    const float* bhh_m     = (const float*)d_in[29];
    const float* W2        = (const float*)d_in[30];
    const float* b2        = (const float*)d_in[31];

    float *px,*py,*pz,*pt1,*pt2,*pts,*prs,*pcb;
    float *pgout,*pggh,*pgog1,*pgog2;
    bf16 *p0hi,*p0lo,*pxhi,*pxlo,*phhi,*phlo,*pwhi,*pwlo;
    cudaGetSymbolAddress((void**)&px,  g_x);
    cudaGetSymbolAddress((void**)&py,  g_y);
    cudaGetSymbolAddress((void**)&pz,  g_z);
    cudaGetSymbolAddress((void**)&pt1, g_t1);
    cudaGetSymbolAddress((void**)&pt2, g_t2);
    cudaGetSymbolAddress((void**)&pts, g_ts);
    cudaGetSymbolAddress((void**)&prs, g_rs);
    cudaGetSymbolAddress((void**)&pcb, g_cb);
    cudaGetSymbolAddress((void**)&pgout, g_gout);
    cudaGetSymbolAddress((void**)&pggh,  g_ggh);
    cudaGetSymbolAddress((void**)&pgog1, g_gog1);
    cudaGetSymbolAddress((void**)&pgog2, g_gog2);
    cudaGetSymbolAddress((void**)&p0hi, g_0hi);
    cudaGetSymbolAddress((void**)&p0lo, g_0lo);
    cudaGetSymbolAddress((void**)&pxhi, g_xhi);
    cudaGetSymbolAddress((void**)&pxlo, g_xlo);
    cudaGetSymbolAddress((void**)&phhi, g_hhi);
    cudaGetSymbolAddress((void**)&phlo, g_hlo);
    cudaGetSymbolAddress((void**)&pwhi, g_whi);
    cudaGetSymbolAddress((void**)&pwlo, g_wlo);

    static int smem_set = 0;
    if (!smem_set) {
        cudaFuncSetAttribute(hgemm_mma, cudaFuncAttributeMaxDynamicSharedMemorySize, MM_SMEM);
        cudaFuncSetAttribute(hgemm_dual, cudaFuncAttributeMaxDynamicSharedMemorySize, MM_SMEM);
        smem_set = 1;
    }

    const int RB = (NN + 127) / 128;
    const int EB   = (NE + 255) / 256;
    const int NB4  = (NN*32 + 255) / 256;
    const int DWB  = (NN*32 + 255) / 256;
    const int AGG  = (NN*32 + 255) / 256;

    WPtrs wp;
    wp.p[0]=W1; wp.p[1]=Wg1; wp.p[2]=Wg2; wp.p[3]=Wih0; wp.p[4]=Whh0;
    wp.p[5]=Wa; wp.p[6]=Wa+128*128; wp.p[7]=Wih_a; wp.p[8]=Wih_a+384*128;
    wp.p[9]=Whh_a; wp.p[10]=Whh_a+384*128; wp.p[11]=Wm;

    // ---- prologue ----
    conv_weights<<<dim3(64, 12), 256>>>(wp);
    conv_act<<<(NN*32 + 255)/256, 256>>>(x0, p0hi, p0lo, NN*32);
    prep_vecs<<<1, 128>>>(Wg1, Wm, att_dst_m);
    hgemm_mma<<<dim3(2, RB), 256, MM_SMEM>>>(p0hi, p0lo, pwhi+OFF_W1, pwlo+OFF_W1,
                                             b1, px, pxhi, pxlo, NN, 64, 128, 1);
    // merged WG1 (leaky, cbias -> py) + WG2 (-> pz): same A = pxhi
    {
        GSet s0 = { pxhi, pxlo, pwhi+OFF_WG1, pwlo+OFF_WG1, pcb,     py, 128, 1 };
        GSet s1 = { pxhi, pxlo, pwhi+OFF_WG2, pwlo+OFF_WG2, nullptr, pz, 128, 0 };
        hgemm_dual<<<dim3(4, RB), 256, MM_SMEM>>>(s0, s1, 2, NN);
    }
    csr_zero<<<(NN + 255)/256, 256>>>();
    csr_hist<<<EB, 256>>>(ei);
    csr_scan<<<1, 1024>>>();
    csr_fill<<<EB, 256>>>(ei);

    // ---- GATEConv ----
    rowdot2<<<DWB, 256>>>(py, att_l, px, att_r, pts, prs, NN);
    gat_agg<<<AGG, 256>>>(pts, prs, pz, bg);
    {
        GSet s0 = { phhi, phlo, pwhi+OFF_WIH0, pwlo+OFF_WIH0, bih0, pt1, 384, 0 };
        GSet s1 = { pxhi, pxlo, pwhi+OFF_WHH0, pwlo+OFF_WHH0, bhh0, pt2, 384, 0 };
        hgemm_dual<<<dim3(12, RB), 256, MM_SMEM>>>(s0, s1, 6, NN);
    }
    gru_elem<<<NB4, 256>>>(pt1, pt2, px, pxhi, pxlo, NN);

    // ---- 2 GATConv layers ----
    for (int l = 0; l < 2; l++) {
        hgemm_mma<<<dim3(2, RB), 256, MM_SMEM>>>(pxhi, pxlo,
                                                 pwhi+OFF_WA+l*16384, pwlo+OFF_WA+l*16384,
                                                 nullptr, pz, nullptr, nullptr, NN, 128, 128, 0);
        rowdot2<<<DWB, 256>>>(pz, att_src_a + l*128, pz, att_dst_a + l*128, pts, prs, NN);
        gat_agg<<<AGG, 256>>>(pts, prs, pz, ba + l*128);
        {
            GSet s0 = { phhi, phlo, pwhi+OFF_WIHA+l*49152, pwlo+OFF_WIHA+l*49152,
                        bih_a + l*384, pt1, 384, 0 };
            GSet s1 = { pxhi, pxlo, pwhi+OFF_WHHA+l*49152, pwlo+OFF_WHHA+l*49152,
                        bhh_a + l*384, pt2, 384, 0 };
            hgemm_dual<<<dim3(12, RB), 256, MM_SMEM>>>(s0, s1, 6, NN);
        }
        gru_elem<<<NB4, 256>>>(pt1, pt2, px, pxhi, pxlo, NN);
    }

    // ---- attentive readout ----
    seg_offsets<<<5, 256>>>(batch);
    readout_sum<<<NG, 128>>>(px);
    hgemm_mma<<<dim3(2, RB), 256, MM_SMEM>>>(pxhi, pxlo, pwhi+OFF_WM, pwlo+OFF_WM,
                                             nullptr, pz, nullptr, nullptr, NN, 128, 128, 0);
    rowdot2<<<DWB, 256>>>(pz, att_src_m, pz, att_src_m, pts, nullptr, NN);

    for (int t = 0; t < 3; t++) {
        readout_attn<<<NG, 128>>>(pts, pz, bm);
        {
            SSet s0 = { pggh,  Wih_m, bih_m, pgog1 };
            SSet s1 = { pgout, Whh_m, bhh_m, pgog2 };
            sgemm_dual<<<dim3(12, 16), 256>>>(s0, s1, 6, NG);
        }
        gru_elem<<<(NG*32 + 255)/256, 256>>>(pgog1, pgog2, pgout, nullptr, nullptr, NG);
    }

    final_out<<<NG, 128>>>(W2, b2, (float*)d_out);
}

// round 16
// speedup vs baseline: 1.3108x; 1.0038x over previous
#include <cuda_runtime.h>
#include <cuda_bf16.h>
#include <cstdint>
#include <math.h>

#define NN 50000
#define NE 800000
#define NG 1024

typedef __nv_bfloat16 bf16;
typedef __nv_bfloat162 bf162;

// ---------------- scratch (device globals; no allocation allowed) ----------------
__device__ float g_x [NN*128];
__device__ float g_y [NN*128];
__device__ float g_z [NN*128];
__device__ float g_t1[NN*384];
__device__ float g_t2[NN*384];
__device__ float g_ts[NN];
__device__ float g_rs[NN];
__device__ float g_e [NE];
__device__ int   g_deg[NN];
__device__ int   g_cur[NN];
__device__ int   g_rowptr[NN+1];
__device__ int   g_csr[NE];
__device__ int   g_off[NG+1];
__device__ float g_cb[128];
__device__ float g_vd[128];
__device__ float g_vsrc[3][128];   // layer0, layer1, readout (Wm^T att_src_m)
__device__ float g_vdst[2][128];   // layer0, layer1
__device__ float g_gout[NG*128];
__device__ float g_ggh [NG*128];
__device__ float g_gog1[NG*384];
__device__ float g_gog2[NG*384];

// bf16 hi/lo activation buffers
__device__ __align__(16) bf16 g_0hi[NN*64];
__device__ __align__(16) bf16 g_0lo[NN*64];
__device__ __align__(16) bf16 g_xhi[NN*128];
__device__ __align__(16) bf16 g_xlo[NN*128];
__device__ __align__(16) bf16 g_hhi[NN*128];
__device__ __align__(16) bf16 g_hlo[NN*128];

// bf16 hi/lo weight scratch (packed, ld = K)
#define OFF_W1    0
#define OFF_WG1   8192
#define OFF_WG2   24576
#define OFF_WIH0  40960
#define OFF_WHH0  90112
#define OFF_WA    139264
#define OFF_WIHA  172032
#define OFF_WHHA  270336
#define OFF_WM    368640
#define W_TOTAL   385024
__device__ __align__(16) bf16 g_whi[W_TOTAL];
__device__ __align__(16) bf16 g_wlo[W_TOTAL];

// ---------------- helpers ----------------
__device__ __forceinline__ float leakyf(float v){ return v >= 0.f ? v : 0.01f*v; }
__device__ __forceinline__ float sigmf (float v){ return 1.f/(1.f+expf(-v)); }
__device__ __forceinline__ float eluf  (float v){ return v > 0.f ? v : (expf(v)-1.f); }

// =======================================================================
// weight conversion: all 12 node-GEMM weights -> packed bf16 hi/lo
// =======================================================================
struct WPtrs { const float* p[12]; };

__global__ void conv_weights(WPtrs wp)
{
    const int rows[12] = {128,128,128,384,384,128,128,384,384,384,384,128};
    const int cols[12] = { 64,128,128,128,128,128,128,128,128,128,128,128};
    const int ldws[12] = { 64,153,128,128,128,128,128,128,128,128,128,128};
    const int offs[12] = {OFF_W1,OFF_WG1,OFF_WG2,OFF_WIH0,OFF_WHH0,
                          OFF_WA,OFF_WA+16384,OFF_WIHA,OFF_WIHA+49152,
                          OFF_WHHA,OFF_WHHA+49152,OFF_WM};
    int s = blockIdx.y;
    const float* src = wp.p[s];
    int n = rows[s]*cols[s];
    for (int i = blockIdx.x*blockDim.x + threadIdx.x; i < n; i += gridDim.x*blockDim.x) {
        int r = i / cols[s], c = i - r*cols[s];
        float v = src[(size_t)r*ldws[s] + c];
        bf16 h = __float2bfloat16(v);
        g_whi[offs[s] + i] = h;
        g_wlo[offs[s] + i] = __float2bfloat16(v - __bfloat162float(h));
    }
}

__global__ void conv_act(const float* __restrict__ src, bf16* __restrict__ hi,
                         bf16* __restrict__ lo, int n2)
{
    int i = blockIdx.x*blockDim.x + threadIdx.x;
    if (i >= n2) return;
    float2 v = *(const float2*)(src + i*2);
    bf16 hx = __float2bfloat16(v.x), hy = __float2bfloat16(v.y);
    *(bf162*)(hi + i*2) = __halves2bfloat162(hx, hy);
    *(bf162*)(lo + i*2) = __halves2bfloat162(__float2bfloat16(v.x - __bfloat162float(hx)),
                                             __float2bfloat16(v.y - __bfloat162float(hy)));
}

// cb[k], ṽd = Wm^T att_dst_m, plus linear attention vectors:
//   vsrc[l] = Wa[l]^T att_src_a[l], vdst[l] = Wa[l]^T att_dst_a[l], vsrc[2] = Wm^T att_src_m
__global__ void prep_vecs(const float* __restrict__ Wg1, const float* __restrict__ Wm,
                          const float* __restrict__ att_dst_m,
                          const float* __restrict__ Wa,
                          const float* __restrict__ att_src_a,
                          const float* __restrict__ att_dst_a,
                          const float* __restrict__ att_src_m)
{
    int k = threadIdx.x;
    float c = 0.f;
    for (int j = 128; j < 153; j++) c += Wg1[k*153 + j];
    g_cb[k] = c;

    float vd = 0.f, vsm = 0.f;
    for (int r = 0; r < 128; r++) {
        vd  = fmaf(Wm[r*128 + k], att_dst_m[r], vd);
        vsm = fmaf(Wm[r*128 + k], att_src_m[r], vsm);
    }
    g_vd[k] = vd;
    g_vsrc[2][k] = vsm;

    #pragma unroll
    for (int l = 0; l < 2; l++) {
        const float* W = Wa + l*16384;
        float vs = 0.f, vdd = 0.f;
        for (int r = 0; r < 128; r++) {
            vs  = fmaf(W[r*128 + k], att_src_a[l*128 + r], vs);
            vdd = fmaf(W[r*128 + k], att_dst_a[l*128 + r], vdd);
        }
        g_vsrc[l][k] = vs;
        g_vdst[l][k] = vdd;
    }
}

// =======================================================================
// bf16 split-precision tensor-core GEMM body (measured-best R11 structure)
// =======================================================================
#define LDA 72
#define ABUF (128*LDA)
#define WBUF (64*LDA)
#define MM_SMEM ((2*ABUF + 2*WBUF)*2)   // 55296 bytes

__device__ __forceinline__ void mma16816(float* c, const uint32_t* a, const uint32_t* b){
    asm volatile(
        "mma.sync.aligned.m16n8k16.row.col.f32.bf16.bf16.f32 "
        "{%0,%1,%2,%3}, {%4,%5,%6,%7}, {%8,%9}, {%0,%1,%2,%3};\n"
        : "+f"(c[0]), "+f"(c[1]), "+f"(c[2]), "+f"(c[3])
        : "r"(a[0]), "r"(a[1]), "r"(a[2]), "r"(a[3]), "r"(b[0]), "r"(b[1]));
}
__device__ __forceinline__ void ldsm4(uint32_t* r, uint32_t addr){
    asm volatile("ldmatrix.sync.aligned.m8n8.x4.shared.b16 {%0,%1,%2,%3}, [%4];"
        : "=r"(r[0]), "=r"(r[1]), "=r"(r[2]), "=r"(r[3]) : "r"(addr));
}
__device__ __forceinline__ void cpa16(uint32_t dst, const void* src, int sz){
    asm volatile("cp.async.cg.shared.global [%0], [%1], 16, %2;"
        :: "r"(dst), "l"(src), "r"(sz));
}

__device__ __forceinline__ void gemm_body(
    const bf16* __restrict__ Ahi, const bf16* __restrict__ Alo,
    const bf16* __restrict__ Whi, const bf16* __restrict__ Wlo,
    const float* __restrict__ bias, float* __restrict__ C,
    bf16* __restrict__ Chi, bf16* __restrict__ Clo,
    int N, int K, int Ko, int act, int row0, int col0, bf16* sm)
{
    bf16* sAhi = sm;
    bf16* sAlo = sm + ABUF;
    bf16* sBhi = sm + 2*ABUF;
    bf16* sBlo = sm + 2*ABUF + WBUF;

    const int tid  = threadIdx.x;
    const int wid  = tid >> 5, lane = tid & 31;
    const int wm   = wid & 3,  wn   = wid >> 2;
    const int gid  = lane >> 2, tig = lane & 3;

    const int arow = wm*32 + (lane & 15);
    const int acol = (lane >> 4) << 3;
    const int brow = wn*32 + ((lane >> 4) << 3) + (lane & 7);
    const int bcol = ((lane >> 3) & 1) << 3;

    const uint32_t uAhi = (uint32_t)__cvta_generic_to_shared(sAhi);
    const uint32_t uAlo = (uint32_t)__cvta_generic_to_shared(sAlo);
    const uint32_t uBhi = (uint32_t)__cvta_generic_to_shared(sBhi);
    const uint32_t uBlo = (uint32_t)__cvta_generic_to_shared(sBlo);

    float acc[2][4][4];
    #pragma unroll
    for (int mt = 0; mt < 2; mt++)
        #pragma unroll
        for (int nt = 0; nt < 4; nt++)
            #pragma unroll
            for (int q = 0; q < 4; q++) acc[mt][nt][q] = 0.f;

    for (int kc = 0; kc < K; kc += 64) {
        #pragma unroll
        for (int i = tid; i < 1024; i += 256) {
            int r = i >> 3, cc = (i & 7) * 8;
            int gr = row0 + r;
            int grc = gr < N ? gr : 0;
            int sz = gr < N ? 16 : 0;
            uint32_t d = (uint32_t)(r*LDA + cc)*2;
            cpa16(uAhi + d, Ahi + (size_t)grc*K + kc + cc, sz);
            cpa16(uAlo + d, Alo + (size_t)grc*K + kc + cc, sz);
        }
        #pragma unroll
        for (int i = tid; i < 512; i += 256) {
            int r = i >> 3, cc = (i & 7) * 8;
            uint32_t d = (uint32_t)(r*LDA + cc)*2;
            cpa16(uBhi + d, Whi + (size_t)(col0 + r)*K + kc + cc, 16);
            cpa16(uBlo + d, Wlo + (size_t)(col0 + r)*K + kc + cc, 16);
        }
        asm volatile("cp.async.commit_group;");
        asm volatile("cp.async.wait_group 0;");
        __syncthreads();

        const uint32_t At[3] = { uAhi, uAhi, uAlo };
        const uint32_t Bt[3] = { uBhi, uBlo, uBhi };

        #pragma unroll 1
        for (int t = 0; t < 3; t++) {
            uint32_t abase = At[t] + (uint32_t)(arow*LDA + acol)*2;
            uint32_t bbase = Bt[t] + (uint32_t)(brow*LDA + bcol)*2;
            #pragma unroll
            for (int k0 = 0; k0 < 64; k0 += 16) {
                uint32_t af[2][4], bf[2][4];
                ldsm4(af[0], abase + k0*2);
                ldsm4(af[1], abase + (16*LDA + k0)*2);
                ldsm4(bf[0], bbase + k0*2);
                ldsm4(bf[1], bbase + (16*LDA + k0)*2);
                #pragma unroll
                for (int mt = 0; mt < 2; mt++) {
                    mma16816(acc[mt][0], af[mt], bf[0]);
                    mma16816(acc[mt][1], af[mt], bf[0] + 2);
                    mma16816(acc[mt][2], af[mt], bf[1]);
                    mma16816(acc[mt][3], af[mt], bf[1] + 2);
                }
            }
        }
        __syncthreads();
    }

    #pragma unroll
    for (int mt = 0; mt < 2; mt++) {
        int gr0 = row0 + wm*32 + mt*16 + gid;
        #pragma unroll
        for (int half = 0; half < 2; half++) {
            int r = gr0 + half*8;
            if (r >= N) continue;
            #pragma unroll
            for (int nt = 0; nt < 4; nt++) {
                int gc = col0 + wn*32 + nt*8 + tig*2;
                float v0 = acc[mt][nt][half*2+0];
                float v1 = acc[mt][nt][half*2+1];
                if (bias) { v0 += bias[gc]; v1 += bias[gc+1]; }
                if (act == 1) { v0 = leakyf(v0); v1 = leakyf(v1); }
                *(float2*)(C + (size_t)r*Ko + gc) = make_float2(v0, v1);
                if (Chi) {
                    bf16 h0 = __float2bfloat16(v0), h1 = __float2bfloat16(v1);
                    *(bf162*)(Chi + (size_t)r*Ko + gc) = __halves2bfloat162(h0, h1);
                    *(bf162*)(Clo + (size_t)r*Ko + gc) =
                        __halves2bfloat162(__float2bfloat16(v0 - __bfloat162float(h0)),
                                           __float2bfloat16(v1 - __bfloat162float(h1)));
                }
            }
        }
    }
}

__global__ void __launch_bounds__(256, 4)
hgemm_mma(const bf16* __restrict__ Ahi, const bf16* __restrict__ Alo,
          const bf16* __restrict__ Whi, const bf16* __restrict__ Wlo,
          const float* __restrict__ bias, float* __restrict__ C,
          bf16* __restrict__ Chi, bf16* __restrict__ Clo,
          int N, int K, int Ko, int act)
{
    extern __shared__ bf16 sm[];
    gemm_body(Ahi, Alo, Whi, Wlo, bias, C, Chi, Clo, N, K, Ko, act,
              blockIdx.y*128, blockIdx.x*64, sm);
}

// generalized dual launch: blockIdx.x < tiles0 -> set0, else set1. K=128.
struct GSet { const bf16 *Ahi, *Alo, *Whi, *Wlo; const float* bias; float* C; int Ko, act; };

__global__ void __launch_bounds__(256, 4)
hgemm_dual(GSet s0, GSet s1, int tiles0, int N)
{
    extern __shared__ bf16 sm[];
    bool second = blockIdx.x >= tiles0;
    const GSet& s = second ? s1 : s0;
    int col0 = (blockIdx.x - (second ? tiles0 : 0)) * 64;
    gemm_body(s.Ahi, s.Alo, s.Whi, s.Wlo, s.bias, s.C, nullptr, nullptr,
              N, 128, s.Ko, s.act, blockIdx.y*128, col0, sm);
}

// ---------------- small GEMM body (graph-level, fp32, 64x64 tiles) ----------------
__device__ __forceinline__ void sgemm_body(
    const float* __restrict__ A, const float* __restrict__ W,
    const float* __restrict__ bias, float* __restrict__ C,
    int N, int M, int ldw, int Ko, int act, int row0, int col0)
{
    __shared__ float sA[16][64];
    __shared__ float sB[16][64];
    const int tid = threadIdx.x;
    const int tx = tid & 15, ty = tid >> 4;

    float acc[4][4];
    #pragma unroll
    for (int i = 0; i < 4; i++)
        #pragma unroll
        for (int j = 0; j < 4; j++) acc[i][j] = 0.f;

    const int r  = tid >> 2;
    const int kq = (tid & 3) * 4;

    for (int k0 = 0; k0 < M; k0 += 16) {
        int gr = row0 + r;
        float4 av;
        if (gr < N) av = *(const float4*)(A + (size_t)gr*M + k0 + kq);
        else        av = make_float4(0.f,0.f,0.f,0.f);
        sA[kq+0][r]=av.x; sA[kq+1][r]=av.y; sA[kq+2][r]=av.z; sA[kq+3][r]=av.w;

        float4 bv = *(const float4*)(W + (size_t)(col0 + r)*ldw + k0 + kq);
        sB[kq+0][r]=bv.x; sB[kq+1][r]=bv.y; sB[kq+2][r]=bv.z; sB[kq+3][r]=bv.w;
        __syncthreads();

        #pragma unroll
        for (int kk = 0; kk < 16; kk++) {
            float ra[4], rb[4];
            #pragma unroll
            for (int i = 0; i < 4; i++) ra[i] = sA[kk][ty*4+i];
            #pragma unroll
            for (int j = 0; j < 4; j++) rb[j] = sB[kk][tx*4+j];
            #pragma unroll
            for (int i = 0; i < 4; i++)
                #pragma unroll
                for (int j = 0; j < 4; j++) acc[i][j] = fmaf(ra[i], rb[j], acc[i][j]);
        }
        __syncthreads();
    }

    #pragma unroll
    for (int i = 0; i < 4; i++) {
        int gr = row0 + ty*4 + i;
        if (gr >= N) continue;
        #pragma unroll
        for (int j = 0; j < 4; j++) {
            int gc = col0 + tx*4 + j;
            float v = acc[i][j];
            if (bias) v += bias[gc];
            if (act == 1) v = leakyf(v);
            C[(size_t)gr*Ko + gc] = v;
        }
    }
}

struct SSet { const float *A, *W, *bias; float* C; };

__global__ void sgemm_dual(SSet s0, SSet s1, int tiles0, int N)
{
    bool second = blockIdx.x >= tiles0;
    const SSet& s = second ? s1 : s0;
    int col0 = (blockIdx.x - (second ? tiles0 : 0)) * 64;
    sgemm_body(s.A, s.W, s.bias, s.C, N, 128, 128, 384, 0, blockIdx.y*64, col0);
}

// ---------------- per-node dual dot (GATE layer only) ----------------
__global__ void rowdot2(const float* __restrict__ A, const float* __restrict__ v1,
                        const float* __restrict__ B, const float* __restrict__ v2,
                        float* __restrict__ o1, float* __restrict__ o2, int N)
{
    int gw = (blockIdx.x*blockDim.x + threadIdx.x) >> 5;
    int lane = threadIdx.x & 31;
    if (gw >= N) return;
    const float4 a = *(const float4*)(A + (size_t)gw*128 + lane*4);
    const float4 b = *(const float4*)(B + (size_t)gw*128 + lane*4);
    const float4 u = *(const float4*)(v1 + lane*4);
    const float4 w = *(const float4*)(v2 + lane*4);
    float s1 = a.x*u.x + a.y*u.y + a.z*u.z + a.w*u.w;
    float s2 = b.x*w.x + b.y*w.y + b.z*w.z + b.w*w.w;
    #pragma unroll
    for (int o = 16; o; o >>= 1) {
        s1 += __shfl_xor_sync(0xffffffffu, s1, o);
        s2 += __shfl_xor_sync(0xffffffffu, s2, o);
    }
    if (lane == 0) { o1[gw] = s1; if (o2) o2[gw] = s2; }
}

// ======================= CSR build =======================
__global__ void csr_zero()
{
    int i = blockIdx.x*blockDim.x + threadIdx.x;
    if (i < NN) { g_deg[i] = 0; g_cur[i] = 0; }
}

__global__ void csr_hist(const int* __restrict__ ei)
{
    int e = blockIdx.x*blockDim.x + threadIdx.x;
    if (e >= NE) return;
    atomicAdd(&g_deg[ei[NE+e]], 1);
}

__global__ void __launch_bounds__(1024) csr_scan()
{
    __shared__ int wsum[32];
    const int t = threadIdx.x, lane = t & 31, w = t >> 5;
    const int CH = (NN + 1023) / 1024;
    const int base = t*CH;
    const int end = min(base + CH, NN);
    int sum = 0;
    for (int i = base; i < end; i++) sum += g_deg[i];
    int v = sum;
    #pragma unroll
    for (int o = 1; o < 32; o <<= 1) {
        int u = __shfl_up_sync(0xffffffffu, v, o);
        if (lane >= o) v += u;
    }
    if (lane == 31) wsum[w] = v;
    __syncthreads();
    if (w == 0) {
        int s = wsum[lane];
        #pragma unroll
        for (int o = 1; o < 32; o <<= 1) {
            int u = __shfl_up_sync(0xffffffffu, s, o);
            if (lane >= o) s += u;
        }
        wsum[lane] = s;
    }
    __syncthreads();
    int off = v - sum + (w ? wsum[w-1] : 0);
    for (int i = base; i < end; i++) { g_rowptr[i] = off; off += g_deg[i]; }
    if (t == 1023) g_rowptr[NN] = NE;
}

__global__ void csr_fill(const int* __restrict__ ei)
{
    int e = blockIdx.x*blockDim.x + threadIdx.x;
    if (e >= NE) return;
    int d = ei[NE+e];
    int slot = atomicAdd(&g_cur[d], 1);
    g_csr[g_rowptr[d] + slot] = ei[e];
}

// =======================================================================
// Fused GAT aggregation: warp per dst node; unroll-2 edge loop.
// =======================================================================
__global__ void __launch_bounds__(256)
gat_agg(const float* __restrict__ as, const float* __restrict__ ad,
        const float* __restrict__ msg, const float* __restrict__ bias)
{
    int w = (blockIdx.x*blockDim.x + threadIdx.x) >> 5;
    int lane = threadIdx.x & 31;
    if (w >= NN) return;
    const int s = g_rowptr[w], e = g_rowptr[w+1];
    const float adv = ad[w];

    float mx = -3.402823e38f;
    for (int j = s + lane; j < e; j += 32)
        mx = fmaxf(mx, leakyf(as[g_csr[j]] + adv));
    #pragma unroll
    for (int o = 16; o; o >>= 1)
        mx = fmaxf(mx, __shfl_xor_sync(0xffffffffu, mx, o));

    float ssum = 0.f;
    float4 acc = make_float4(0.f,0.f,0.f,0.f);
    int j = s;
    for (; j + 1 < e; j += 2) {
        int s0 = g_csr[j], s1 = g_csr[j+1];
        float w0 = expf(leakyf(as[s0] + adv) - mx);
        float w1 = expf(leakyf(as[s1] + adv) - mx);
        ssum += w0 + w1;
        float4 m0 = *(const float4*)(msg + (size_t)s0*128 + lane*4);
        float4 m1 = *(const float4*)(msg + (size_t)s1*128 + lane*4);
        acc.x = fmaf(w0, m0.x, fmaf(w1, m1.x, acc.x));
        acc.y = fmaf(w0, m0.y, fmaf(w1, m1.y, acc.y));
        acc.z = fmaf(w0, m0.z, fmaf(w1, m1.z, acc.z));
        acc.w = fmaf(w0, m0.w, fmaf(w1, m1.w, acc.w));
    }
    if (j < e) {
        int s0 = g_csr[j];
        float w0 = expf(leakyf(as[s0] + adv) - mx);
        ssum += w0;
        float4 m0 = *(const float4*)(msg + (size_t)s0*128 + lane*4);
        acc.x = fmaf(w0, m0.x, acc.x);
        acc.y = fmaf(w0, m0.y, acc.y);
        acc.z = fmaf(w0, m0.z, acc.z);
        acc.w = fmaf(w0, m0.w, acc.w);
    }
    float inv = 1.f / (ssum + 1e-16f);
    float4 bv = *(const float4*)(bias + lane*4);
    float o0 = eluf(acc.x*inv + bv.x);
    float o1 = eluf(acc.y*inv + bv.y);
    float o2 = eluf(acc.z*inv + bv.z);
    float o3 = eluf(acc.w*inv + bv.w);

    size_t base = (size_t)w*128 + lane*4;
    bf16 h0 = __float2bfloat16(o0), h1 = __float2bfloat16(o1);
    bf16 h2 = __float2bfloat16(o2), h3 = __float2bfloat16(o3);
    *(bf162*)(g_hhi + base)     = __halves2bfloat162(h0, h1);
    *(bf162*)(g_hhi + base + 2) = __halves2bfloat162(h2, h3);
    *(bf162*)(g_hlo + base)     = __halves2bfloat162(__float2bfloat16(o0 - __bfloat162float(h0)),
                                                     __float2bfloat16(o1 - __bfloat162float(h1)));
    *(bf162*)(g_hlo + base + 2) = __halves2bfloat162(__float2bfloat16(o2 - __bfloat162float(h2)),
                                                     __float2bfloat16(o3 - __bfloat162float(h3)));
}

// ---------------- elementwise GRU + fused next-stage attention dots ----------------
// Each warp covers one full 128-wide row (32 lanes x float4). If v1 != null,
// compute o1[n] = x_new[n]·v1 (and o2 = x_new[n]·v2 if v2 != null) via shuffles.
__global__ void gru_elem(const float* __restrict__ gi, const float* __restrict__ gh,
                         float* __restrict__ hstate, bf16* __restrict__ ohi,
                         bf16* __restrict__ olo,
                         const float* __restrict__ v1, const float* __restrict__ v2,
                         float* __restrict__ o1, float* __restrict__ o2, int rows)
{
    int i = blockIdx.x*blockDim.x + threadIdx.x;
    if (i >= rows*32) return;
    int n = i >> 5, q = (i & 31) * 4;
    int lane = i & 31;
    const float* a = gi + (size_t)n*384 + q;
    const float* b = gh + (size_t)n*384 + q;
    float4 ai = *(const float4*)(a);
    float4 az = *(const float4*)(a + 128);
    float4 an = *(const float4*)(a + 256);
    float4 bi = *(const float4*)(b);
    float4 bz = *(const float4*)(b + 128);
    float4 bn = *(const float4*)(b + 256);
    float4 hv = *(float4*)(hstate + (size_t)n*128 + q);

    float r, z, nn, v;
    r = sigmf(ai.x + bi.x); z = sigmf(az.x + bz.x); nn = tanhf(an.x + r*bn.x);
    v = (1.f - z)*nn + z*hv.x; hv.x = v > 0.f ? v : 0.f;
    r = sigmf(ai.y + bi.y); z = sigmf(az.y + bz.y); nn = tanhf(an.y + r*bn.y);
    v = (1.f - z)*nn + z*hv.y; hv.y = v > 0.f ? v : 0.f;
    r = sigmf(ai.z + bi.z); z = sigmf(az.z + bz.z); nn = tanhf(an.z + r*bn.z);
    v = (1.f - z)*nn + z*hv.z; hv.z = v > 0.f ? v : 0.f;
    r = sigmf(ai.w + bi.w); z = sigmf(az.w + bz.w); nn = tanhf(an.w + r*bn.w);
    v = (1.f - z)*nn + z*hv.w; hv.w = v > 0.f ? v : 0.f;

    *(float4*)(hstate + (size_t)n*128 + q) = hv;

    if (ohi) {
        size_t base = (size_t)n*128 + q;
        bf16 h0 = __float2bfloat16(hv.x), h1 = __float2bfloat16(hv.y);
        bf16 h2 = __float2bfloat16(hv.z), h3 = __float2bfloat16(hv.w);
        *(bf162*)(ohi + base)     = __halves2bfloat162(h0, h1);
        *(bf162*)(ohi + base + 2) = __halves2bfloat162(h2, h3);
        *(bf162*)(olo + base)     = __halves2bfloat162(__float2bfloat16(hv.x - __bfloat162float(h0)),
                                                       __float2bfloat16(hv.y - __bfloat162float(h1)));
        *(bf162*)(olo + base + 2) = __halves2bfloat162(__float2bfloat16(hv.z - __bfloat162float(h2)),
                                                       __float2bfloat16(hv.w - __bfloat162float(h3)));
    }

    if (v1) {
        float4 u = *(const float4*)(v1 + q);
        float d1 = hv.x*u.x + hv.y*u.y + hv.z*u.z + hv.w*u.w;
        float d2 = 0.f;
        if (v2) {
            float4 w2 = *(const float4*)(v2 + q);
            d2 = hv.x*w2.x + hv.y*w2.y + hv.z*w2.z + hv.w*w2.w;
        }
        #pragma unroll
        for (int o = 16; o; o >>= 1) {
            d1 += __shfl_xor_sync(0xffffffffu, d1, o);
            d2 += __shfl_xor_sync(0xffffffffu, d2, o);
        }
        if (lane == 0) { o1[n] = d1; if (v2) o2[n] = d2; }
    }
}

// ---------------- readout ----------------
__global__ void seg_offsets(const int* __restrict__ batch)
{
    int g = blockIdx.x*blockDim.x + threadIdx.x;
    if (g > NG) return;
    int lo = 0, hi = NN;
    while (lo < hi) { int mid = (lo+hi) >> 1; if (batch[mid] < g) lo = mid+1; else hi = mid; }
    g_off[g] = lo;
}

__global__ void readout_sum(const float* __restrict__ x)
{
    int g = blockIdx.x, k = threadIdx.x;
    int s = g_off[g], e = g_off[g+1];
    float acc = 0.f;
    for (int n = s; n < e; n++) acc += x[(size_t)n*128 + k];
    g_gout[g*128 + k] = acc > 0.f ? acc : 0.f;
}

// fused: adst = gout[g]·ṽ (block reduce), then per-graph softmax + aggregate + elu
__global__ void readout_attn(const float* __restrict__ asrc, const float* __restrict__ xt,
                             const float* __restrict__ bm)
{
    int g = blockIdx.x, tid = threadIdx.x;   // 128 threads
    int s = g_off[g], e = g_off[g+1];
    __shared__ float red[4];

    float dv = g_gout[g*128 + tid] * g_vd[tid];
    #pragma unroll
    for (int o = 16; o; o >>= 1) dv += __shfl_xor_sync(0xffffffffu, dv, o);
    if ((tid & 31) == 0) red[tid >> 5] = dv;
    __syncthreads();
    float ad = red[0] + red[1] + red[2] + red[3];
    __syncthreads();

    float mx = -3.402823e38f;
    for (int n = s + tid; n < e; n += 128) mx = fmaxf(mx, leakyf(asrc[n] + ad));
    #pragma unroll
    for (int o = 16; o; o >>= 1) mx = fmaxf(mx, __shfl_xor_sync(0xffffffffu, mx, o));
    if ((tid & 31) == 0) red[tid >> 5] = mx;
    __syncthreads();
    mx = fmaxf(fmaxf(red[0], red[1]), fmaxf(red[2], red[3]));
    __syncthreads();

    float sm = 0.f;
    for (int n = s + tid; n < e; n += 128) {
        float ee = expf(leakyf(asrc[n] + ad) - mx);
        g_e[n] = ee;
        sm += ee;
    }
    #pragma unroll
    for (int o = 16; o; o >>= 1) sm += __shfl_xor_sync(0xffffffffu, sm, o);
    if ((tid & 31) == 0) red[tid >> 5] = sm;
    __syncthreads();
    sm = red[0] + red[1] + red[2] + red[3];
    float inv = 1.f / (sm + 1e-16f);

    float acc = 0.f;
    for (int n = s; n < e; n++) acc = fmaf(xt[(size_t)n*128 + tid], g_e[n], acc);
    g_ggh[g*128 + tid] = eluf(acc*inv + bm[tid]);
}

__global__ void final_out(const float* __restrict__ W2, const float* __restrict__ b2,
                          float* __restrict__ out)
{
    int g = blockIdx.x, tid = threadIdx.x;
    __shared__ float red[4];
    float s = g_gout[g*128 + tid] * W2[tid];
    #pragma unroll
    for (int o = 16; o; o >>= 1) s += __shfl_xor_sync(0xffffffffu, s, o);
    if ((tid & 31) == 0) red[tid >> 5] = s;
    __syncthreads();
    if (tid == 0) out[g] = red[0] + red[1] + red[2] + red[3] + b2[0];
}

// ---------------- host orchestration ----------------
extern "C" void kernel_launch(void* const* d_in, const int* in_sizes, int n_in,
                              void* d_out, int out_size)
{
    const float* x0    = (const float*)d_in[0];
    const int*   ei    = (const int*)  d_in[1];
    const int*   batch = (const int*)  d_in[2];
    const float* W1    = (const float*)d_in[3];
    const float* b1    = (const float*)d_in[4];
    const float* Wg1   = (const float*)d_in[5];
    const float* att_l = (const float*)d_in[6];
    const float* att_r = (const float*)d_in[7];
    const float* Wg2   = (const float*)d_in[8];
    const float* bg    = (const float*)d_in[9];
    const float* Wih0  = (const float*)d_in[10];
    const float* Whh0  = (const float*)d_in[11];
    const float* bih0  = (const float*)d_in[12];
    const float* bhh0  = (const float*)d_in[13];
    const float* Wa        = (const float*)d_in[14];
    const float* att_src_a = (const float*)d_in[15];
    const float* att_dst_a = (const float*)d_in[16];
    const float* ba        = (const float*)d_in[17];
    const float* Wih_a     = (const float*)d_in[18];
    const float* Whh_a     = (const float*)d_in[19];
    const float* bih_a     = (const float*)d_in[20];
    const float* bhh_a     = (const float*)d_in[21];
    const float* Wm        = (const float*)d_in[22];
    const float* att_src_m = (const float*)d_in[23];
    const float* att_dst_m = (const float*)d_in[24];
    const float* bm        = (const float*)d_in[25];
    const float* Wih_m     = (const float*)d_in[26];
    const float* Whh_m     = (const float*)d_in[27];
    const float* bih_m     = (const float*)d_in[28];
    const float* bhh_m     = (const float*)d_in[29];
    const float* W2        = (const float*)d_in[30];
    const float* b2        = (const float*)d_in[31];

    float *px,*py,*pz,*pt1,*pt2,*pts,*prs,*pcb;
    float *pgout,*pggh,*pgog1,*pgog2,*pvsrc,*pvdst;
    bf16 *p0hi,*p0lo,*pxhi,*pxlo,*phhi,*phlo,*pwhi,*pwlo;
    cudaGetSymbolAddress((void**)&px,  g_x);
    cudaGetSymbolAddress((void**)&py,  g_y);
    cudaGetSymbolAddress((void**)&pz,  g_z);
    cudaGetSymbolAddress((void**)&pt1, g_t1);
    cudaGetSymbolAddress((void**)&pt2, g_t2);
    cudaGetSymbolAddress((void**)&pts, g_ts);
    cudaGetSymbolAddress((void**)&prs, g_rs);
    cudaGetSymbolAddress((void**)&pcb, g_cb);
    cudaGetSymbolAddress((void**)&pgout, g_gout);
    cudaGetSymbolAddress((void**)&pggh,  g_ggh);
    cudaGetSymbolAddress((void**)&pgog1, g_gog1);
    cudaGetSymbolAddress((void**)&pgog2, g_gog2);
    cudaGetSymbolAddress((void**)&pvsrc, g_vsrc);
    cudaGetSymbolAddress((void**)&pvdst, g_vdst);
    cudaGetSymbolAddress((void**)&p0hi, g_0hi);
    cudaGetSymbolAddress((void**)&p0lo, g_0lo);
    cudaGetSymbolAddress((void**)&pxhi, g_xhi);
    cudaGetSymbolAddress((void**)&pxlo, g_xlo);
    cudaGetSymbolAddress((void**)&phhi, g_hhi);
    cudaGetSymbolAddress((void**)&phlo, g_hlo);
    cudaGetSymbolAddress((void**)&pwhi, g_whi);
    cudaGetSymbolAddress((void**)&pwlo, g_wlo);

    static int smem_set = 0;
    if (!smem_set) {
        cudaFuncSetAttribute(hgemm_mma, cudaFuncAttributeMaxDynamicSharedMemorySize, MM_SMEM);
        cudaFuncSetAttribute(hgemm_dual, cudaFuncAttributeMaxDynamicSharedMemorySize, MM_SMEM);
        smem_set = 1;
    }

    const int RB = (NN + 127) / 128;
    const int EB   = (NE + 255) / 256;
    const int NB4  = (NN*32 + 255) / 256;
    const int DWB  = (NN*32 + 255) / 256;
    const int AGG  = (NN*32 + 255) / 256;

    WPtrs wp;
    wp.p[0]=W1; wp.p[1]=Wg1; wp.p[2]=Wg2; wp.p[3]=Wih0; wp.p[4]=Whh0;
    wp.p[5]=Wa; wp.p[6]=Wa+128*128; wp.p[7]=Wih_a; wp.p[8]=Wih_a+384*128;
    wp.p[9]=Whh_a; wp.p[10]=Whh_a+384*128; wp.p[11]=Wm;

    // ---- prologue ----
    conv_weights<<<dim3(64, 12), 256>>>(wp);
    conv_act<<<(NN*32 + 255)/256, 256>>>(x0, p0hi, p0lo, NN*32);
    prep_vecs<<<1, 128>>>(Wg1, Wm, att_dst_m, Wa, att_src_a, att_dst_a, att_src_m);
    hgemm_mma<<<dim3(2, RB), 256, MM_SMEM>>>(p0hi, p0lo, pwhi+OFF_W1, pwlo+OFF_W1,
                                             b1, px, pxhi, pxlo, NN, 64, 128, 1);
    // merged WG1 (leaky, cbias -> py) + WG2 (-> pz): same A = pxhi
    {
        GSet s0 = { pxhi, pxlo, pwhi+OFF_WG1, pwlo+OFF_WG1, pcb,     py, 128, 1 };
        GSet s1 = { pxhi, pxlo, pwhi+OFF_WG2, pwlo+OFF_WG2, nullptr, pz, 128, 0 };
        hgemm_dual<<<dim3(4, RB), 256, MM_SMEM>>>(s0, s1, 2, NN);
    }
    csr_zero<<<(NN + 255)/256, 256>>>();
    csr_hist<<<EB, 256>>>(ei);
    csr_scan<<<1, 1024>>>();
    csr_fill<<<EB, 256>>>(ei);

    // ---- GATEConv ----
    rowdot2<<<DWB, 256>>>(py, att_l, px, att_r, pts, prs, NN);
    gat_agg<<<AGG, 256>>>(pts, prs, pz, bg);
    {
        GSet s0 = { phhi, phlo, pwhi+OFF_WIH0, pwlo+OFF_WIH0, bih0, pt1, 384, 0 };
        GSet s1 = { pxhi, pxlo, pwhi+OFF_WHH0, pwlo+OFF_WHH0, bhh0, pt2, 384, 0 };
        hgemm_dual<<<dim3(12, RB), 256, MM_SMEM>>>(s0, s1, 6, NN);
    }
    // gru + fused attention dots for layer 0
    gru_elem<<<NB4, 256>>>(pt1, pt2, px, pxhi, pxlo, pvsrc + 0*128, pvdst + 0*128,
                           pts, prs, NN);

    // ---- 2 GATConv layers ----
    for (int l = 0; l < 2; l++) {
        hgemm_mma<<<dim3(2, RB), 256, MM_SMEM>>>(pxhi, pxlo,
                                                 pwhi+OFF_WA+l*16384, pwlo+OFF_WA+l*16384,
                                                 nullptr, pz, nullptr, nullptr, NN, 128, 128, 0);
        gat_agg<<<AGG, 256>>>(pts, prs, pz, ba + l*128);
        {
            GSet s0 = { phhi, phlo, pwhi+OFF_WIHA+l*49152, pwlo+OFF_WIHA+l*49152,
                        bih_a + l*384, pt1, 384, 0 };
            GSet s1 = { pxhi, pxlo, pwhi+OFF_WHHA+l*49152, pwlo+OFF_WHHA+l*49152,
                        bhh_a + l*384, pt2, 384, 0 };
            hgemm_dual<<<dim3(12, RB), 256, MM_SMEM>>>(s0, s1, 6, NN);
        }
        if (l == 0) {
            // produce logits for layer 1
            gru_elem<<<NB4, 256>>>(pt1, pt2, px, pxhi, pxlo, pvsrc + 1*128, pvdst + 1*128,
                                   pts, prs, NN);
        } else {
            // produce a_src for readout (single dot with Wm^T att_src_m)
            gru_elem<<<NB4, 256>>>(pt1, pt2, px, pxhi, pxlo, pvsrc + 2*128, nullptr,
                                   pts, nullptr, NN);
        }
    }

    // ---- attentive readout ----
    seg_offsets<<<5, 256>>>(batch);
    readout_sum<<<NG, 128>>>(px);
    hgemm_mma<<<dim3(2, RB), 256, MM_SMEM>>>(pxhi, pxlo, pwhi+OFF_WM, pwlo+OFF_WM,
                                             nullptr, pz, nullptr, nullptr, NN, 128, 128, 0);

    for (int t = 0; t < 3; t++) {
        readout_attn<<<NG, 128>>>(pts, pz, bm);
        {
            SSet s0 = { pggh,  Wih_m, bih_m, pgog1 };
            SSet s1 = { pgout, Whh_m, bhh_m, pgog2 };
            sgemm_dual<<<dim3(12, 16), 256>>>(s0, s1, 6, NG);
        }
        gru_elem<<<(NG*32 + 255)/256, 256>>>(pgog1, pgog2, pgout, nullptr, nullptr,
                                             nullptr, nullptr, nullptr, nullptr, NG);
    }

    final_out<<<NG, 128>>>(W2, b2, (float*)d_out);
}